// round 1
// baseline (speedup 1.0000x reference)
#include <cuda_runtime.h>
#include <math.h>

// Problem constants
#define NB 8
#define NS 1024
#define ND 768
#define NH 12
#define NHD 64
#define NM (NB*NS)        // 8192 rows
#define NBH (NB*NH)       // 96 batch-head pairs

// ---------------- scratch (static device globals; no allocation) ----------------
__device__ float g_q   [NM*ND];
__device__ float g_k   [NM*ND];
__device__ float g_v   [NM*ND];
__device__ float g_ctx [NM*ND];
__device__ float g_proj[NM*ND];
__device__ float g_scores[100663296]; // B*H*S*S = 96 * 1024 * 1024

// ---------------- block reduction helpers ----------------
__device__ __forceinline__ float warpSum(float v) {
    #pragma unroll
    for (int o = 16; o; o >>= 1) v += __shfl_xor_sync(0xffffffffu, v, o);
    return v;
}
__device__ __forceinline__ float warpMax(float v) {
    #pragma unroll
    for (int o = 16; o; o >>= 1) v = fmaxf(v, __shfl_xor_sync(0xffffffffu, v, o));
    return v;
}
__device__ __forceinline__ float blockSum(float v) {
    __shared__ float s[8];
    __syncthreads();
    v = warpSum(v);
    if ((threadIdx.x & 31) == 0) s[threadIdx.x >> 5] = v;
    __syncthreads();
    if (threadIdx.x == 0) {
        float t = 0.f;
        #pragma unroll
        for (int i = 0; i < 8; i++) t += s[i];
        s[0] = t;
    }
    __syncthreads();
    return s[0];
}
__device__ __forceinline__ float blockMax(float v) {
    __shared__ float s[8];
    __syncthreads();
    v = warpMax(v);
    if ((threadIdx.x & 31) == 0) s[threadIdx.x >> 5] = v;
    __syncthreads();
    if (threadIdx.x == 0) {
        float t = -3.4e38f;
        #pragma unroll
        for (int i = 0; i < 8; i++) t = fmaxf(t, s[i]);
        s[0] = t;
    }
    __syncthreads();
    return s[0];
}

// ---------------- SGEMM: C[M,N] = A[M,K] @ W[N,K]^T + bias[N] ----------------
// 128x128 tile, BK=8, 256 threads, 8x8 per thread. M%128==0, N%128==0, K%8==0.
__global__ __launch_bounds__(256)
void sgemm_nt_bias(const float* __restrict__ A, const float* __restrict__ W,
                   const float* __restrict__ bias, float* __restrict__ C,
                   int M, int N, int K)
{
    constexpr int BM = 128, BN = 128, BK = 8, TM = 8, TN = 8;
    __shared__ float As[BK][BM];
    __shared__ float Bs[BK][BN];

    const int t    = threadIdx.x;
    const int cRow = blockIdx.y * BM;
    const int cCol = blockIdx.x * BN;

    const int aRow = t >> 1;           // 0..127
    const int aCol = (t & 1) * 4;      // 0 or 4
    const int tx = t & 15;             // 0..15
    const int ty = t >> 4;             // 0..15

    const float* Ag = A + (long)cRow * K;
    const float* Wg = W + (long)cCol * K;

    float acc[TM][TN];
    #pragma unroll
    for (int i = 0; i < TM; i++)
        #pragma unroll
        for (int j = 0; j < TN; j++) acc[i][j] = 0.f;

    for (int kt = 0; kt < K; kt += BK) {
        float4 av = *(const float4*)(Ag + (long)aRow * K + kt + aCol);
        As[aCol + 0][aRow] = av.x;
        As[aCol + 1][aRow] = av.y;
        As[aCol + 2][aRow] = av.z;
        As[aCol + 3][aRow] = av.w;
        float4 wv = *(const float4*)(Wg + (long)aRow * K + kt + aCol);
        Bs[aCol + 0][aRow] = wv.x;
        Bs[aCol + 1][aRow] = wv.y;
        Bs[aCol + 2][aRow] = wv.z;
        Bs[aCol + 3][aRow] = wv.w;
        __syncthreads();

        #pragma unroll
        for (int kk = 0; kk < BK; kk++) {
            float4 a0 = *(const float4*)&As[kk][ty * TM];
            float4 a1 = *(const float4*)&As[kk][ty * TM + 4];
            float4 b0 = *(const float4*)&Bs[kk][tx * TN];
            float4 b1 = *(const float4*)&Bs[kk][tx * TN + 4];
            float ra[TM] = {a0.x, a0.y, a0.z, a0.w, a1.x, a1.y, a1.z, a1.w};
            float rb[TN] = {b0.x, b0.y, b0.z, b0.w, b1.x, b1.y, b1.z, b1.w};
            #pragma unroll
            for (int i = 0; i < TM; i++)
                #pragma unroll
                for (int j = 0; j < TN; j++)
                    acc[i][j] = fmaf(ra[i], rb[j], acc[i][j]);
        }
        __syncthreads();
    }

    float4 bb0 = *(const float4*)(bias + cCol + tx * TN);
    float4 bb1 = *(const float4*)(bias + cCol + tx * TN + 4);
    #pragma unroll
    for (int i = 0; i < TM; i++) {
        float4 o0 = make_float4(acc[i][0] + bb0.x, acc[i][1] + bb0.y,
                                acc[i][2] + bb0.z, acc[i][3] + bb0.w);
        float4 o1 = make_float4(acc[i][4] + bb1.x, acc[i][5] + bb1.y,
                                acc[i][6] + bb1.z, acc[i][7] + bb1.w);
        float* cp = C + (long)(cRow + ty * TM + i) * N + cCol + tx * TN;
        *(float4*)cp       = o0;
        *(float4*)(cp + 4) = o1;
    }
}

// ---------------- scores[b,h,q,k] = Q.K^T/8 + mask[b,k] ----------------
// grid: (S/64, S/64, B*H), 256 threads, 4x4 per thread
__global__ __launch_bounds__(256)
void scores_kernel(const float* __restrict__ Q, const float* __restrict__ Kx,
                   const float* __restrict__ mask, float* __restrict__ Sc)
{
    __shared__ float Qs[64][65];
    __shared__ float Ks[64][65];

    const int bh = blockIdx.z;
    const int b  = bh / NH;
    const int h  = bh % NH;
    const int q0 = blockIdx.y * 64;
    const int k0 = blockIdx.x * 64;
    const int t  = threadIdx.x;
    const int tx = t & 15, ty = t >> 4;

    const float* Qb = Q + (long)b * NS * ND + (long)h * NHD;
    const float* Kb = Kx + (long)b * NS * ND + (long)h * NHD;

    #pragma unroll
    for (int i = 0; i < 4; i++) {
        int f  = t + i * 256;        // 0..1023
        int r  = f >> 4;             // 0..63
        int c4 = (f & 15) * 4;
        float4 qv = *(const float4*)(Qb + (long)(q0 + r) * ND + c4);
        Qs[r][c4 + 0] = qv.x; Qs[r][c4 + 1] = qv.y; Qs[r][c4 + 2] = qv.z; Qs[r][c4 + 3] = qv.w;
        float4 kv = *(const float4*)(Kb + (long)(k0 + r) * ND + c4);
        Ks[r][c4 + 0] = kv.x; Ks[r][c4 + 1] = kv.y; Ks[r][c4 + 2] = kv.z; Ks[r][c4 + 3] = kv.w;
    }
    __syncthreads();

    float acc[4][4];
    #pragma unroll
    for (int i = 0; i < 4; i++)
        #pragma unroll
        for (int j = 0; j < 4; j++) acc[i][j] = 0.f;

    #pragma unroll 8
    for (int kk = 0; kk < 64; kk++) {
        float ra[4], rb[4];
        #pragma unroll
        for (int i = 0; i < 4; i++) ra[i] = Qs[ty * 4 + i][kk];
        #pragma unroll
        for (int j = 0; j < 4; j++) rb[j] = Ks[tx * 4 + j][kk];
        #pragma unroll
        for (int i = 0; i < 4; i++)
            #pragma unroll
            for (int j = 0; j < 4; j++)
                acc[i][j] = fmaf(ra[i], rb[j], acc[i][j]);
    }

    float* out = Sc + (long)bh * NS * NS;
    #pragma unroll
    for (int i = 0; i < 4; i++) {
        int q = q0 + ty * 4 + i;
        #pragma unroll
        for (int j = 0; j < 4; j++) {
            int k = k0 + tx * 4 + j;
            out[(long)q * NS + k] = acc[i][j] * 0.125f + mask[b * NS + k];
        }
    }
}

// ---------------- row softmax over last dim (1024) ----------------
__global__ __launch_bounds__(256)
void softmax_kernel(float* __restrict__ Sc)
{
    float* p = Sc + (long)blockIdx.x * NS;
    const int t = threadIdx.x;
    float4 v = *(const float4*)(p + t * 4);

    float mx = fmaxf(fmaxf(v.x, v.y), fmaxf(v.z, v.w));
    mx = blockMax(mx);

    v.x = expf(v.x - mx); v.y = expf(v.y - mx);
    v.z = expf(v.z - mx); v.w = expf(v.w - mx);
    float sm = blockSum(v.x + v.y + v.z + v.w);
    float inv = 1.0f / sm;
    v.x *= inv; v.y *= inv; v.z *= inv; v.w *= inv;
    *(float4*)(p + t * 4) = v;
}

// ---------------- ctx[b,q,h,d] = head_mask[h] * sum_k P[b,h,q,k] V[b,k,h,d] ----------------
// grid: (S/64, 1, B*H), 256 threads, 4x4 per thread, K looped in 64-chunks
__global__ __launch_bounds__(256)
void ctx_kernel(const float* __restrict__ P, const float* __restrict__ V,
                const float* __restrict__ head_mask, float* __restrict__ Cx)
{
    __shared__ float Ps[64][65];
    __shared__ float Vs[64][65];

    const int bh = blockIdx.z;
    const int b  = bh / NH;
    const int h  = bh % NH;
    const int q0 = blockIdx.x * 64;
    const int t  = threadIdx.x;
    const int tx = t & 15, ty = t >> 4;

    const float* Pb = P + (long)bh * NS * NS;
    const float* Vb = V + (long)b * NS * ND + (long)h * NHD;

    float acc[4][4];
    #pragma unroll
    for (int i = 0; i < 4; i++)
        #pragma unroll
        for (int j = 0; j < 4; j++) acc[i][j] = 0.f;

    for (int kt = 0; kt < NS; kt += 64) {
        #pragma unroll
        for (int i = 0; i < 4; i++) {
            int f  = t + i * 256;
            int r  = f >> 4;
            int c4 = (f & 15) * 4;
            float4 pv = *(const float4*)(Pb + (long)(q0 + r) * NS + kt + c4);
            Ps[r][c4 + 0] = pv.x; Ps[r][c4 + 1] = pv.y; Ps[r][c4 + 2] = pv.z; Ps[r][c4 + 3] = pv.w;
            float4 vv = *(const float4*)(Vb + (long)(kt + r) * ND + c4);
            Vs[r][c4 + 0] = vv.x; Vs[r][c4 + 1] = vv.y; Vs[r][c4 + 2] = vv.z; Vs[r][c4 + 3] = vv.w;
        }
        __syncthreads();

        #pragma unroll 8
        for (int kk = 0; kk < 64; kk++) {
            float ra[4], rb[4];
            #pragma unroll
            for (int i = 0; i < 4; i++) ra[i] = Ps[ty * 4 + i][kk];
            #pragma unroll
            for (int j = 0; j < 4; j++) rb[j] = Vs[kk][tx * 4 + j];
            #pragma unroll
            for (int i = 0; i < 4; i++)
                #pragma unroll
                for (int j = 0; j < 4; j++)
                    acc[i][j] = fmaf(ra[i], rb[j], acc[i][j]);
        }
        __syncthreads();
    }

    const float hm = head_mask[h];
    float* out = Cx + (long)b * NS * ND + (long)h * NHD;
    #pragma unroll
    for (int i = 0; i < 4; i++) {
        int q = q0 + ty * 4 + i;
        #pragma unroll
        for (int j = 0; j < 4; j++) {
            int d = tx * 4 + j;
            out[(long)q * ND + d] = acc[i][j] * hm;
        }
    }
}

// ---------------- residual + LayerNorm ----------------
// one block per row of 768 = 3 * 256
__global__ __launch_bounds__(256)
void ln_kernel(const float* __restrict__ proj, const float* __restrict__ hidden,
               const float* __restrict__ gamma, const float* __restrict__ beta,
               float* __restrict__ out)
{
    const long row = blockIdx.x;
    const int t = threadIdx.x;
    float x[3];
    #pragma unroll
    for (int k = 0; k < 3; k++) {
        long idx = row * ND + t + k * 256;
        x[k] = proj[idx] + hidden[idx];
    }
    float s = x[0] + x[1] + x[2];
    float mu = blockSum(s) * (1.0f / ND);
    float vs = 0.f;
    #pragma unroll
    for (int k = 0; k < 3; k++) { float d = x[k] - mu; vs += d * d; }
    float var = blockSum(vs) * (1.0f / ND);
    float rstd = rsqrtf(var + 1e-12f);
    #pragma unroll
    for (int k = 0; k < 3; k++) {
        int c = t + k * 256;
        out[row * ND + c] = (x[k] - mu) * rstd * gamma[c] + beta[c];
    }
}

// ---------------- launch ----------------
extern "C" void kernel_launch(void* const* d_in, const int* in_sizes, int n_in,
                              void* d_out, int out_size)
{
    const float* hidden    = (const float*)d_in[0];
    const float* attn_mask = (const float*)d_in[1];
    const float* head_mask = (const float*)d_in[2];
    const float* Wq = (const float*)d_in[3];
    const float* bq = (const float*)d_in[4];
    const float* Wk = (const float*)d_in[5];
    const float* bk = (const float*)d_in[6];
    const float* Wv = (const float*)d_in[7];
    const float* bv = (const float*)d_in[8];
    const float* Wo = (const float*)d_in[9];
    const float* bo = (const float*)d_in[10];
    const float* gamma = (const float*)d_in[11];
    const float* beta  = (const float*)d_in[12];
    float* out = (float*)d_out;

    void *pq, *pk, *pv, *pc, *pp, *ps;
    cudaGetSymbolAddress(&pq, g_q);
    cudaGetSymbolAddress(&pk, g_k);
    cudaGetSymbolAddress(&pv, g_v);
    cudaGetSymbolAddress(&pc, g_ctx);
    cudaGetSymbolAddress(&pp, g_proj);
    cudaGetSymbolAddress(&ps, g_scores);
    float* q  = (float*)pq;
    float* k  = (float*)pk;
    float* v  = (float*)pv;
    float* cx = (float*)pc;
    float* pr = (float*)pp;
    float* sc = (float*)ps;

    dim3 gGemm(ND / 128, NM / 128);   // (6, 64)
    sgemm_nt_bias<<<gGemm, 256>>>(hidden, Wq, bq, q, NM, ND, ND);
    sgemm_nt_bias<<<gGemm, 256>>>(hidden, Wk, bk, k, NM, ND, ND);
    sgemm_nt_bias<<<gGemm, 256>>>(hidden, Wv, bv, v, NM, ND, ND);

    dim3 gSc(NS / 64, NS / 64, NBH);  // (16, 16, 96)
    scores_kernel<<<gSc, 256>>>(q, k, attn_mask, sc);

    softmax_kernel<<<NBH * NS, 256>>>(sc);

    dim3 gCtx(NS / 64, 1, NBH);       // (16, 1, 96)
    ctx_kernel<<<gCtx, 256>>>(sc, v, head_mask, cx);

    sgemm_nt_bias<<<gGemm, 256>>>(cx, Wo, bo, pr, NM, ND, ND);

    ln_kernel<<<NM, 256>>>(pr, hidden, gamma, beta, out);
}

// round 2
// speedup vs baseline: 1.3396x; 1.3396x over previous
#include <cuda_runtime.h>
#include <math.h>

// Problem constants
#define NB 8
#define NS 1024
#define ND 768
#define NH 12
#define NHD 64
#define NM (NB*NS)        // 8192 rows
#define NBH (NB*NH)       // 96 batch-head pairs

// ---------------- scratch (static device globals; no allocation) ----------------
__device__ float g_q   [NM*ND];
__device__ float g_k   [NM*ND];
__device__ float g_v   [NM*ND];
__device__ float g_ctx [NM*ND];
__device__ float g_proj[NM*ND];

// ---------------- block reduction helpers ----------------
__device__ __forceinline__ float warpSum(float v) {
    #pragma unroll
    for (int o = 16; o; o >>= 1) v += __shfl_xor_sync(0xffffffffu, v, o);
    return v;
}
__device__ __forceinline__ float blockSum(float v) {
    __shared__ float s[8];
    __syncthreads();
    v = warpSum(v);
    if ((threadIdx.x & 31) == 0) s[threadIdx.x >> 5] = v;
    __syncthreads();
    if (threadIdx.x == 0) {
        float t = 0.f;
        #pragma unroll
        for (int i = 0; i < 8; i++) t += s[i];
        s[0] = t;
    }
    __syncthreads();
    return s[0];
}

// ---------------- SGEMM: C[M,N] = A[M,K] @ W[N,K]^T + bias[N] ----------------
// 128x128 tile, BK=8, 256 threads, 8x8 per thread. Double-buffered SMEM with
// global->register prefetch; one __syncthreads per K-step.
__global__ __launch_bounds__(256)
void sgemm_nt_bias(const float* __restrict__ A, const float* __restrict__ W,
                   const float* __restrict__ bias, float* __restrict__ C,
                   int M, int N, int K)
{
    constexpr int BM = 128, BN = 128, BK = 8, TM = 8, TN = 8;
    __shared__ float As[2][BK][BM];
    __shared__ float Bs[2][BK][BN];

    const int t    = threadIdx.x;
    const int cRow = blockIdx.y * BM;
    const int cCol = blockIdx.x * BN;

    const int aRow = t >> 1;           // 0..127
    const int aCol = (t & 1) * 4;      // 0 or 4
    const int tx = t & 15;             // 0..15
    const int ty = t >> 4;             // 0..15

    const float* Ag = A + (long)(cRow + aRow) * K + aCol;
    const float* Wg = W + (long)(cCol + aRow) * K + aCol;

    float4 av = *(const float4*)Ag;
    float4 wv = *(const float4*)Wg;
    As[0][aCol + 0][aRow] = av.x;
    As[0][aCol + 1][aRow] = av.y;
    As[0][aCol + 2][aRow] = av.z;
    As[0][aCol + 3][aRow] = av.w;
    Bs[0][aCol + 0][aRow] = wv.x;
    Bs[0][aCol + 1][aRow] = wv.y;
    Bs[0][aCol + 2][aRow] = wv.z;
    Bs[0][aCol + 3][aRow] = wv.w;
    __syncthreads();

    float acc[TM][TN];
    #pragma unroll
    for (int i = 0; i < TM; i++)
        #pragma unroll
        for (int j = 0; j < TN; j++) acc[i][j] = 0.f;

    int buf = 0;
    for (int kt = 0; kt < K; kt += BK) {
        const bool more = (kt + BK) < K;
        if (more) {
            av = *(const float4*)(Ag + kt + BK);
            wv = *(const float4*)(Wg + kt + BK);
        }

        #pragma unroll
        for (int kk = 0; kk < BK; kk++) {
            float4 a0 = *(const float4*)&As[buf][kk][ty * TM];
            float4 a1 = *(const float4*)&As[buf][kk][ty * TM + 4];
            float4 b0 = *(const float4*)&Bs[buf][kk][tx * TN];
            float4 b1 = *(const float4*)&Bs[buf][kk][tx * TN + 4];
            float ra[TM] = {a0.x, a0.y, a0.z, a0.w, a1.x, a1.y, a1.z, a1.w};
            float rb[TN] = {b0.x, b0.y, b0.z, b0.w, b1.x, b1.y, b1.z, b1.w};
            #pragma unroll
            for (int i = 0; i < TM; i++)
                #pragma unroll
                for (int j = 0; j < TN; j++)
                    acc[i][j] = fmaf(ra[i], rb[j], acc[i][j]);
        }

        if (more) {
            As[buf ^ 1][aCol + 0][aRow] = av.x;
            As[buf ^ 1][aCol + 1][aRow] = av.y;
            As[buf ^ 1][aCol + 2][aRow] = av.z;
            As[buf ^ 1][aCol + 3][aRow] = av.w;
            Bs[buf ^ 1][aCol + 0][aRow] = wv.x;
            Bs[buf ^ 1][aCol + 1][aRow] = wv.y;
            Bs[buf ^ 1][aCol + 2][aRow] = wv.z;
            Bs[buf ^ 1][aCol + 3][aRow] = wv.w;
            __syncthreads();
            buf ^= 1;
        }
    }

    float4 bb0 = *(const float4*)(bias + cCol + tx * TN);
    float4 bb1 = *(const float4*)(bias + cCol + tx * TN + 4);
    #pragma unroll
    for (int i = 0; i < TM; i++) {
        float4 o0 = make_float4(acc[i][0] + bb0.x, acc[i][1] + bb0.y,
                                acc[i][2] + bb0.z, acc[i][3] + bb0.w);
        float4 o1 = make_float4(acc[i][4] + bb1.x, acc[i][5] + bb1.y,
                                acc[i][6] + bb1.z, acc[i][7] + bb1.w);
        float* cp = C + (long)(cRow + ty * TM + i) * N + cCol + tx * TN;
        *(float4*)cp       = o0;
        *(float4*)(cp + 4) = o1;
    }
}

// ---------------- Fused flash attention ----------------
// One block = 128 q-rows of one (b,h). Loops over 16 kv-tiles of 64.
// scores (QK^T/8 + mask) -> online softmax -> O += P@V, head_mask folded in.
// 256 threads: tx = 0..15 (4 cols each), ty = 0..15 (8 rows each).
__global__ __launch_bounds__(256, 2)
void flash_kernel(const float* __restrict__ Q, const float* __restrict__ Kx,
                  const float* __restrict__ Vx, const float* __restrict__ mask,
                  const float* __restrict__ head_mask, float* __restrict__ Cx)
{
    extern __shared__ float smem[];
    float* Qs = smem;                 // [64][132]  Q^T: Qs[d*132 + row]
    float* Ks = Qs + 64 * 132;        // [64][68]   K^T: Ks[d*68 + col]
    float* Vs = Ks + 64 * 68;         // [64][68]   Vs[k*68 + d]
    float* Ps = Vs + 64 * 68;         // [128][68]  Ps[row*68 + k]

    const int bh = blockIdx.y;
    const int b  = bh / NH;
    const int h  = bh % NH;
    const int q0 = blockIdx.x * 128;
    const int t  = threadIdx.x;
    const int tx = t & 15, ty = t >> 4;

    const float* Qg = Q  + (long)b * NS * ND + (long)h * NHD;
    const float* Kg = Kx + (long)b * NS * ND + (long)h * NHD;
    const float* Vg = Vx + (long)b * NS * ND + (long)h * NHD;

    // Load Q tile [128 x 64] transposed into Qs[d][row]
    {
        const int r = t >> 1;
        const int dbase = (t & 1) * 32;
        #pragma unroll
        for (int i = 0; i < 8; i++) {
            int d0 = dbase + i * 4;
            float4 qv = *(const float4*)(Qg + (long)(q0 + r) * ND + d0);
            Qs[(d0 + 0) * 132 + r] = qv.x;
            Qs[(d0 + 1) * 132 + r] = qv.y;
            Qs[(d0 + 2) * 132 + r] = qv.z;
            Qs[(d0 + 3) * 132 + r] = qv.w;
        }
    }

    float o[8][4];
    float m[8], l[8];
    #pragma unroll
    for (int i = 0; i < 8; i++) {
        m[i] = -3.4e38f;
        l[i] = 0.f;
        #pragma unroll
        for (int j = 0; j < 4; j++) o[i][j] = 0.f;
    }

    for (int k0 = 0; k0 < NS; k0 += 64) {
        __syncthreads();   // protect Ks/Vs overwrite vs previous O-phase reads

        // Load K (transposed) and V (natural) tiles [64 x 64]
        {
            const int r = t >> 2;
            const int dbase = (t & 3) * 16;
            #pragma unroll
            for (int i = 0; i < 4; i++) {
                int d0 = dbase + i * 4;
                float4 kv = *(const float4*)(Kg + (long)(k0 + r) * ND + d0);
                Ks[(d0 + 0) * 68 + r] = kv.x;
                Ks[(d0 + 1) * 68 + r] = kv.y;
                Ks[(d0 + 2) * 68 + r] = kv.z;
                Ks[(d0 + 3) * 68 + r] = kv.w;
                float4 vv = *(const float4*)(Vg + (long)(k0 + r) * ND + d0);
                *(float4*)&Vs[r * 68 + d0] = vv;
            }
        }
        __syncthreads();

        // S = Q @ K^T : 8x4 fragment per thread
        float acc[8][4];
        #pragma unroll
        for (int i = 0; i < 8; i++)
            #pragma unroll
            for (int j = 0; j < 4; j++) acc[i][j] = 0.f;

        #pragma unroll 8
        for (int d = 0; d < 64; d++) {
            float4 a0 = *(const float4*)&Qs[d * 132 + ty * 8];
            float4 a1 = *(const float4*)&Qs[d * 132 + ty * 8 + 4];
            float4 bv = *(const float4*)&Ks[d * 68 + tx * 4];
            float ra[8] = {a0.x, a0.y, a0.z, a0.w, a1.x, a1.y, a1.z, a1.w};
            float rb[4] = {bv.x, bv.y, bv.z, bv.w};
            #pragma unroll
            for (int i = 0; i < 8; i++)
                #pragma unroll
                for (int j = 0; j < 4; j++)
                    acc[i][j] = fmaf(ra[i], rb[j], acc[i][j]);
        }

        // scale + mask, then online softmax update (rows reduce over tx group)
        float4 mk = *(const float4*)(mask + b * NS + k0 + tx * 4);
        float mkj[4] = {mk.x, mk.y, mk.z, mk.w};

        #pragma unroll
        for (int i = 0; i < 8; i++) {
            #pragma unroll
            for (int j = 0; j < 4; j++)
                acc[i][j] = fmaf(acc[i][j], 0.125f, mkj[j]);

            float mx = fmaxf(fmaxf(acc[i][0], acc[i][1]), fmaxf(acc[i][2], acc[i][3]));
            #pragma unroll
            for (int ofs = 1; ofs < 16; ofs <<= 1)
                mx = fmaxf(mx, __shfl_xor_sync(0xffffffffu, mx, ofs));

            float mnew = fmaxf(m[i], mx);
            float corr = __expf(m[i] - mnew);

            float p0 = __expf(acc[i][0] - mnew);
            float p1 = __expf(acc[i][1] - mnew);
            float p2 = __expf(acc[i][2] - mnew);
            float p3 = __expf(acc[i][3] - mnew);
            *(float4*)&Ps[(ty * 8 + i) * 68 + tx * 4] = make_float4(p0, p1, p2, p3);

            float ls = p0 + p1 + p2 + p3;
            #pragma unroll
            for (int ofs = 1; ofs < 16; ofs <<= 1)
                ls += __shfl_xor_sync(0xffffffffu, ls, ofs);

            m[i] = mnew;
            l[i] = l[i] * corr + ls;
            #pragma unroll
            for (int j = 0; j < 4; j++) o[i][j] *= corr;
        }
        __syncthreads();

        // O += P @ V
        #pragma unroll 8
        for (int kk = 0; kk < 64; kk++) {
            float4 bv = *(const float4*)&Vs[kk * 68 + tx * 4];
            float rb[4] = {bv.x, bv.y, bv.z, bv.w};
            float ra[8];
            #pragma unroll
            for (int i = 0; i < 8; i++) ra[i] = Ps[(ty * 8 + i) * 68 + kk];
            #pragma unroll
            for (int i = 0; i < 8; i++)
                #pragma unroll
                for (int j = 0; j < 4; j++)
                    o[i][j] = fmaf(ra[i], rb[j], o[i][j]);
        }
    }

    // epilogue: normalize, head_mask, write ctx[b, q, h*64 + d]
    const float hm = head_mask[h];
    #pragma unroll
    for (int i = 0; i < 8; i++) {
        float inv = hm / l[i];
        float* outp = Cx + ((long)b * NS + q0 + ty * 8 + i) * ND + h * NHD + tx * 4;
        *(float4*)outp = make_float4(o[i][0] * inv, o[i][1] * inv,
                                     o[i][2] * inv, o[i][3] * inv);
    }
}

// ---------------- residual + LayerNorm ----------------
__global__ __launch_bounds__(256)
void ln_kernel(const float* __restrict__ proj, const float* __restrict__ hidden,
               const float* __restrict__ gamma, const float* __restrict__ beta,
               float* __restrict__ out)
{
    const long row = blockIdx.x;
    const int t = threadIdx.x;
    float x[3];
    #pragma unroll
    for (int k = 0; k < 3; k++) {
        long idx = row * ND + t + k * 256;
        x[k] = proj[idx] + hidden[idx];
    }
    float s = x[0] + x[1] + x[2];
    float mu = blockSum(s) * (1.0f / ND);
    float vs = 0.f;
    #pragma unroll
    for (int k = 0; k < 3; k++) { float d = x[k] - mu; vs += d * d; }
    float var = blockSum(vs) * (1.0f / ND);
    float rstd = rsqrtf(var + 1e-12f);
    #pragma unroll
    for (int k = 0; k < 3; k++) {
        int c = t + k * 256;
        out[row * ND + c] = (x[k] - mu) * rstd * gamma[c] + beta[c];
    }
}

// ---------------- launch ----------------
extern "C" void kernel_launch(void* const* d_in, const int* in_sizes, int n_in,
                              void* d_out, int out_size)
{
    const float* hidden    = (const float*)d_in[0];
    const float* attn_mask = (const float*)d_in[1];
    const float* head_mask = (const float*)d_in[2];
    const float* Wq = (const float*)d_in[3];
    const float* bq = (const float*)d_in[4];
    const float* Wk = (const float*)d_in[5];
    const float* bk = (const float*)d_in[6];
    const float* Wv = (const float*)d_in[7];
    const float* bv = (const float*)d_in[8];
    const float* Wo = (const float*)d_in[9];
    const float* bo = (const float*)d_in[10];
    const float* gamma = (const float*)d_in[11];
    const float* beta  = (const float*)d_in[12];
    float* out = (float*)d_out;

    void *pq, *pk, *pv, *pc, *pp;
    cudaGetSymbolAddress(&pq, g_q);
    cudaGetSymbolAddress(&pk, g_k);
    cudaGetSymbolAddress(&pv, g_v);
    cudaGetSymbolAddress(&pc, g_ctx);
    cudaGetSymbolAddress(&pp, g_proj);
    float* q  = (float*)pq;
    float* k  = (float*)pk;
    float* v  = (float*)pv;
    float* cx = (float*)pc;
    float* pr = (float*)pp;

    static int smem_set = 0;
    const int FLASH_SMEM = (64*132 + 64*68 + 64*68 + 128*68) * 4;  // 103424 B
    if (!smem_set) {
        cudaFuncSetAttribute(flash_kernel,
                             cudaFuncAttributeMaxDynamicSharedMemorySize, FLASH_SMEM);
        smem_set = 1;
    }

    dim3 gGemm(ND / 128, NM / 128);   // (6, 64)
    sgemm_nt_bias<<<gGemm, 256>>>(hidden, Wq, bq, q, NM, ND, ND);
    sgemm_nt_bias<<<gGemm, 256>>>(hidden, Wk, bk, k, NM, ND, ND);
    sgemm_nt_bias<<<gGemm, 256>>>(hidden, Wv, bv, v, NM, ND, ND);

    dim3 gF(NS / 128, NBH);           // (8, 96)
    flash_kernel<<<gF, 256, FLASH_SMEM>>>(q, k, v, attn_mask, head_mask, cx);

    sgemm_nt_bias<<<gGemm, 256>>>(cx, Wo, bo, pr, NM, ND, ND);

    ln_kernel<<<NM, 256>>>(pr, hidden, gamma, beta, out);
}

// round 3
// speedup vs baseline: 2.1973x; 1.6402x over previous
#include <cuda_runtime.h>
#include <math.h>
#include <stdint.h>

// Problem constants
#define NB 8
#define NS 1024
#define ND 768
#define NH 12
#define NHD 64
#define NM (NB*NS)        // 8192 rows
#define NBH (NB*NH)       // 96 batch-head pairs

// ---------------- scratch (static device globals; no allocation) ----------------
__device__ float g_q   [NM*ND];
__device__ float g_k   [NM*ND];
__device__ float g_v   [NM*ND];
__device__ float g_ctx [NM*ND];
__device__ float g_proj[NM*ND];

// ---------------- helpers ----------------
__device__ __forceinline__ float warpSum(float v) {
    #pragma unroll
    for (int o = 16; o; o >>= 1) v += __shfl_xor_sync(0xffffffffu, v, o);
    return v;
}
__device__ __forceinline__ float blockSum(float v) {
    __shared__ float s[8];
    __syncthreads();
    v = warpSum(v);
    if ((threadIdx.x & 31) == 0) s[threadIdx.x >> 5] = v;
    __syncthreads();
    if (threadIdx.x == 0) {
        float t = 0.f;
        #pragma unroll
        for (int i = 0; i < 8; i++) t += s[i];
        s[0] = t;
    }
    __syncthreads();
    return s[0];
}

__device__ __forceinline__ uint32_t f2tf32(float x) {
    uint32_t r;
    asm("cvt.rna.tf32.f32 %0, %1;" : "=r"(r) : "f"(x));
    return r;
}

__device__ __forceinline__ void mma_tf32(float d[4], const uint32_t a[4],
                                         const uint32_t b0, const uint32_t b1) {
    asm volatile(
        "mma.sync.aligned.m16n8k8.row.col.f32.tf32.tf32.f32 "
        "{%0,%1,%2,%3}, {%4,%5,%6,%7}, {%8,%9}, {%0,%1,%2,%3};\n"
        : "+f"(d[0]), "+f"(d[1]), "+f"(d[2]), "+f"(d[3])
        : "r"(a[0]), "r"(a[1]), "r"(a[2]), "r"(a[3]),
          "r"(b0), "r"(b1));
}

// ---------------- TF32 tensor-core GEMM ----------------
// C[M,768] = A[M,768] @ W[N,768]^T + bias.  BM=BN=128, BK=32, 256 threads.
// 8 warps: warpM = warp>>1 (4), warpN = warp&1 (2); warp tile 32x64.
// SMEM row stride 36 words -> fragment loads are bank-conflict-free.
#define GK 768
#define GBK 32
#define SROW 36

__global__ __launch_bounds__(256)
void tf32_gemm_nt_bias(const float* __restrict__ A, const float* __restrict__ W,
                       const float* __restrict__ bias, float* __restrict__ C,
                       int M, int N)
{
    extern __shared__ uint32_t sm[];
    uint32_t* As = sm;                 // [2][128][SROW]
    uint32_t* Bs = sm + 2 * 128 * SROW;

    const int t     = threadIdx.x;
    const int warp  = t >> 5;
    const int lane  = t & 31;
    const int warpM = warp >> 1;       // 0..3
    const int warpN = warp & 1;        // 0..1
    const int cRow  = blockIdx.y * 128;
    const int cCol  = blockIdx.x * 128;

    const int ldRow = t >> 3;          // 0..31
    const int ldCol = (t & 7) * 4;     // 0,4,...,28

    const float* Ag = A + (long)(cRow + ldRow) * GK + ldCol;
    const float* Wg = W + (long)(cCol + ldRow) * GK + ldCol;

    // ---- initial tile: gmem -> cvt -> smem buf 0 ----
    #pragma unroll
    for (int p = 0; p < 4; p++) {
        float4 av = *(const float4*)(Ag + (long)p * 32 * GK);
        float4 wv = *(const float4*)(Wg + (long)p * 32 * GK);
        uint32_t* ap = &As[(p * 32 + ldRow) * SROW + ldCol];
        uint32_t* bp = &Bs[(p * 32 + ldRow) * SROW + ldCol];
        ap[0] = f2tf32(av.x); ap[1] = f2tf32(av.y); ap[2] = f2tf32(av.z); ap[3] = f2tf32(av.w);
        bp[0] = f2tf32(wv.x); bp[1] = f2tf32(wv.y); bp[2] = f2tf32(wv.z); bp[3] = f2tf32(wv.w);
    }
    __syncthreads();

    float acc[2][8][4];
    #pragma unroll
    for (int i = 0; i < 2; i++)
        #pragma unroll
        for (int j = 0; j < 8; j++)
            #pragma unroll
            for (int r = 0; r < 4; r++) acc[i][j][r] = 0.f;

    const int lq = lane >> 2;   // 0..7
    const int lr = lane & 3;    // 0..3

    int buf = 0;
    for (int kt = 0; kt < GK; kt += GBK) {
        const bool more = (kt + GBK) < GK;
        float4 pa[4], pb[4];
        if (more) {
            #pragma unroll
            for (int p = 0; p < 4; p++) {
                pa[p] = *(const float4*)(Ag + (long)p * 32 * GK + kt + GBK);
                pb[p] = *(const float4*)(Wg + (long)p * 32 * GK + kt + GBK);
            }
        }

        const uint32_t* Ab = As + buf * 128 * SROW;
        const uint32_t* Bb = Bs + buf * 128 * SROW;

        #pragma unroll
        for (int ks = 0; ks < 4; ks++) {
            const int k0 = ks * 8;
            uint32_t afr[2][4];
            #pragma unroll
            for (int mt = 0; mt < 2; mt++) {
                const int ar = warpM * 32 + mt * 16 + lq;
                afr[mt][0] = Ab[ar * SROW + k0 + lr];
                afr[mt][1] = Ab[(ar + 8) * SROW + k0 + lr];
                afr[mt][2] = Ab[ar * SROW + k0 + 4 + lr];
                afr[mt][3] = Ab[(ar + 8) * SROW + k0 + 4 + lr];
            }
            #pragma unroll
            for (int nt = 0; nt < 8; nt++) {
                const int br = warpN * 64 + nt * 8 + lq;
                uint32_t b0 = Bb[br * SROW + k0 + lr];
                uint32_t b1 = Bb[br * SROW + k0 + 4 + lr];
                mma_tf32(acc[0][nt], afr[0], b0, b1);
                mma_tf32(acc[1][nt], afr[1], b0, b1);
            }
        }

        if (more) {
            uint32_t* Ad = As + (buf ^ 1) * 128 * SROW;
            uint32_t* Bd = Bs + (buf ^ 1) * 128 * SROW;
            #pragma unroll
            for (int p = 0; p < 4; p++) {
                uint32_t* ap = &Ad[(p * 32 + ldRow) * SROW + ldCol];
                uint32_t* bp = &Bd[(p * 32 + ldRow) * SROW + ldCol];
                ap[0] = f2tf32(pa[p].x); ap[1] = f2tf32(pa[p].y);
                ap[2] = f2tf32(pa[p].z); ap[3] = f2tf32(pa[p].w);
                bp[0] = f2tf32(pb[p].x); bp[1] = f2tf32(pb[p].y);
                bp[2] = f2tf32(pb[p].z); bp[3] = f2tf32(pb[p].w);
            }
            __syncthreads();
            buf ^= 1;
        }
    }

    // ---- epilogue: bias add + store ----
    #pragma unroll
    for (int nt = 0; nt < 8; nt++) {
        const int col = cCol + warpN * 64 + nt * 8 + lr * 2;
        const float2 bb = *(const float2*)(bias + col);
        #pragma unroll
        for (int mt = 0; mt < 2; mt++) {
            const int row = cRow + warpM * 32 + mt * 16 + lq;
            float2 r0 = make_float2(acc[mt][nt][0] + bb.x, acc[mt][nt][1] + bb.y);
            float2 r1 = make_float2(acc[mt][nt][2] + bb.x, acc[mt][nt][3] + bb.y);
            *(float2*)(C + (long)row * N + col)       = r0;
            *(float2*)(C + (long)(row + 8) * N + col) = r1;
        }
    }
}

// ---------------- Fused flash attention (unchanged from round 2) ----------------
__global__ __launch_bounds__(256, 2)
void flash_kernel(const float* __restrict__ Q, const float* __restrict__ Kx,
                  const float* __restrict__ Vx, const float* __restrict__ mask,
                  const float* __restrict__ head_mask, float* __restrict__ Cx)
{
    extern __shared__ float smem[];
    float* Qs = smem;                 // [64][132]  Q^T
    float* Ks = Qs + 64 * 132;        // [64][68]   K^T
    float* Vs = Ks + 64 * 68;         // [64][68]
    float* Ps = Vs + 64 * 68;         // [128][68]

    const int bh = blockIdx.y;
    const int b  = bh / NH;
    const int h  = bh % NH;
    const int q0 = blockIdx.x * 128;
    const int t  = threadIdx.x;
    const int tx = t & 15, ty = t >> 4;

    const float* Qg = Q  + (long)b * NS * ND + (long)h * NHD;
    const float* Kg = Kx + (long)b * NS * ND + (long)h * NHD;
    const float* Vg = Vx + (long)b * NS * ND + (long)h * NHD;

    {
        const int r = t >> 1;
        const int dbase = (t & 1) * 32;
        #pragma unroll
        for (int i = 0; i < 8; i++) {
            int d0 = dbase + i * 4;
            float4 qv = *(const float4*)(Qg + (long)(q0 + r) * ND + d0);
            Qs[(d0 + 0) * 132 + r] = qv.x;
            Qs[(d0 + 1) * 132 + r] = qv.y;
            Qs[(d0 + 2) * 132 + r] = qv.z;
            Qs[(d0 + 3) * 132 + r] = qv.w;
        }
    }

    float o[8][4];
    float m[8], l[8];
    #pragma unroll
    for (int i = 0; i < 8; i++) {
        m[i] = -3.4e38f;
        l[i] = 0.f;
        #pragma unroll
        for (int j = 0; j < 4; j++) o[i][j] = 0.f;
    }

    for (int k0 = 0; k0 < NS; k0 += 64) {
        __syncthreads();
        {
            const int r = t >> 2;
            const int dbase = (t & 3) * 16;
            #pragma unroll
            for (int i = 0; i < 4; i++) {
                int d0 = dbase + i * 4;
                float4 kv = *(const float4*)(Kg + (long)(k0 + r) * ND + d0);
                Ks[(d0 + 0) * 68 + r] = kv.x;
                Ks[(d0 + 1) * 68 + r] = kv.y;
                Ks[(d0 + 2) * 68 + r] = kv.z;
                Ks[(d0 + 3) * 68 + r] = kv.w;
                float4 vv = *(const float4*)(Vg + (long)(k0 + r) * ND + d0);
                *(float4*)&Vs[r * 68 + d0] = vv;
            }
        }
        __syncthreads();

        float acc[8][4];
        #pragma unroll
        for (int i = 0; i < 8; i++)
            #pragma unroll
            for (int j = 0; j < 4; j++) acc[i][j] = 0.f;

        #pragma unroll 8
        for (int d = 0; d < 64; d++) {
            float4 a0 = *(const float4*)&Qs[d * 132 + ty * 8];
            float4 a1 = *(const float4*)&Qs[d * 132 + ty * 8 + 4];
            float4 bv = *(const float4*)&Ks[d * 68 + tx * 4];
            float ra[8] = {a0.x, a0.y, a0.z, a0.w, a1.x, a1.y, a1.z, a1.w};
            float rb[4] = {bv.x, bv.y, bv.z, bv.w};
            #pragma unroll
            for (int i = 0; i < 8; i++)
                #pragma unroll
                for (int j = 0; j < 4; j++)
                    acc[i][j] = fmaf(ra[i], rb[j], acc[i][j]);
        }

        float4 mk = *(const float4*)(mask + b * NS + k0 + tx * 4);
        float mkj[4] = {mk.x, mk.y, mk.z, mk.w};

        #pragma unroll
        for (int i = 0; i < 8; i++) {
            #pragma unroll
            for (int j = 0; j < 4; j++)
                acc[i][j] = fmaf(acc[i][j], 0.125f, mkj[j]);

            float mx = fmaxf(fmaxf(acc[i][0], acc[i][1]), fmaxf(acc[i][2], acc[i][3]));
            #pragma unroll
            for (int ofs = 1; ofs < 16; ofs <<= 1)
                mx = fmaxf(mx, __shfl_xor_sync(0xffffffffu, mx, ofs));

            float mnew = fmaxf(m[i], mx);
            float corr = __expf(m[i] - mnew);

            float p0 = __expf(acc[i][0] - mnew);
            float p1 = __expf(acc[i][1] - mnew);
            float p2 = __expf(acc[i][2] - mnew);
            float p3 = __expf(acc[i][3] - mnew);
            *(float4*)&Ps[(ty * 8 + i) * 68 + tx * 4] = make_float4(p0, p1, p2, p3);

            float ls = p0 + p1 + p2 + p3;
            #pragma unroll
            for (int ofs = 1; ofs < 16; ofs <<= 1)
                ls += __shfl_xor_sync(0xffffffffu, ls, ofs);

            m[i] = mnew;
            l[i] = l[i] * corr + ls;
            #pragma unroll
            for (int j = 0; j < 4; j++) o[i][j] *= corr;
        }
        __syncthreads();

        #pragma unroll 8
        for (int kk = 0; kk < 64; kk++) {
            float4 bv = *(const float4*)&Vs[kk * 68 + tx * 4];
            float rb[4] = {bv.x, bv.y, bv.z, bv.w};
            float ra[8];
            #pragma unroll
            for (int i = 0; i < 8; i++) ra[i] = Ps[(ty * 8 + i) * 68 + kk];
            #pragma unroll
            for (int i = 0; i < 8; i++)
                #pragma unroll
                for (int j = 0; j < 4; j++)
                    o[i][j] = fmaf(ra[i], rb[j], o[i][j]);
        }
    }

    const float hm = head_mask[h];
    #pragma unroll
    for (int i = 0; i < 8; i++) {
        float inv = hm / l[i];
        float* outp = Cx + ((long)b * NS + q0 + ty * 8 + i) * ND + h * NHD + tx * 4;
        *(float4*)outp = make_float4(o[i][0] * inv, o[i][1] * inv,
                                     o[i][2] * inv, o[i][3] * inv);
    }
}

// ---------------- residual + LayerNorm ----------------
__global__ __launch_bounds__(256)
void ln_kernel(const float* __restrict__ proj, const float* __restrict__ hidden,
               const float* __restrict__ gamma, const float* __restrict__ beta,
               float* __restrict__ out)
{
    const long row = blockIdx.x;
    const int t = threadIdx.x;
    float x[3];
    #pragma unroll
    for (int k = 0; k < 3; k++) {
        long idx = row * ND + t + k * 256;
        x[k] = proj[idx] + hidden[idx];
    }
    float s = x[0] + x[1] + x[2];
    float mu = blockSum(s) * (1.0f / ND);
    float vs = 0.f;
    #pragma unroll
    for (int k = 0; k < 3; k++) { float d = x[k] - mu; vs += d * d; }
    float var = blockSum(vs) * (1.0f / ND);
    float rstd = rsqrtf(var + 1e-12f);
    #pragma unroll
    for (int k = 0; k < 3; k++) {
        int c = t + k * 256;
        out[row * ND + c] = (x[k] - mu) * rstd * gamma[c] + beta[c];
    }
}

// ---------------- launch ----------------
extern "C" void kernel_launch(void* const* d_in, const int* in_sizes, int n_in,
                              void* d_out, int out_size)
{
    const float* hidden    = (const float*)d_in[0];
    const float* attn_mask = (const float*)d_in[1];
    const float* head_mask = (const float*)d_in[2];
    const float* Wq = (const float*)d_in[3];
    const float* bq = (const float*)d_in[4];
    const float* Wk = (const float*)d_in[5];
    const float* bk = (const float*)d_in[6];
    const float* Wv = (const float*)d_in[7];
    const float* bv = (const float*)d_in[8];
    const float* Wo = (const float*)d_in[9];
    const float* bo = (const float*)d_in[10];
    const float* gamma = (const float*)d_in[11];
    const float* beta  = (const float*)d_in[12];
    float* out = (float*)d_out;

    void *pq, *pk, *pv, *pc, *pp;
    cudaGetSymbolAddress(&pq, g_q);
    cudaGetSymbolAddress(&pk, g_k);
    cudaGetSymbolAddress(&pv, g_v);
    cudaGetSymbolAddress(&pc, g_ctx);
    cudaGetSymbolAddress(&pp, g_proj);
    float* q  = (float*)pq;
    float* k  = (float*)pk;
    float* v  = (float*)pv;
    float* cx = (float*)pc;
    float* pr = (float*)pp;

    const int FLASH_SMEM = (64*132 + 64*68 + 64*68 + 128*68) * 4;  // 103424 B
    const int GEMM_SMEM  = 4 * 128 * SROW * 4;                     // 73728 B
    static int attr_set = 0;
    if (!attr_set) {
        cudaFuncSetAttribute(flash_kernel,
                             cudaFuncAttributeMaxDynamicSharedMemorySize, FLASH_SMEM);
        cudaFuncSetAttribute(tf32_gemm_nt_bias,
                             cudaFuncAttributeMaxDynamicSharedMemorySize, GEMM_SMEM);
        attr_set = 1;
    }

    dim3 gGemm(ND / 128, NM / 128);   // (6, 64)
    tf32_gemm_nt_bias<<<gGemm, 256, GEMM_SMEM>>>(hidden, Wq, bq, q, NM, ND);
    tf32_gemm_nt_bias<<<gGemm, 256, GEMM_SMEM>>>(hidden, Wk, bk, k, NM, ND);
    tf32_gemm_nt_bias<<<gGemm, 256, GEMM_SMEM>>>(hidden, Wv, bv, v, NM, ND);

    dim3 gF(NS / 128, NBH);           // (8, 96)
    flash_kernel<<<gF, 256, FLASH_SMEM>>>(q, k, v, attn_mask, head_mask, cx);

    tf32_gemm_nt_bias<<<gGemm, 256, GEMM_SMEM>>>(cx, Wo, bo, pr, NM, ND);

    ln_kernel<<<NM, 256>>>(pr, hidden, gamma, beta, out);
}

// round 4
// speedup vs baseline: 3.5576x; 1.6191x over previous
#include <cuda_runtime.h>
#include <math.h>
#include <stdint.h>

// Problem constants
#define NB 8
#define NS 1024
#define ND 768
#define NH 12
#define NHD 64
#define NM (NB*NS)        // 8192 rows
#define NBH (NB*NH)       // 96 batch-head pairs

// ---------------- scratch (static device globals; no allocation) ----------------
__device__ float g_q   [NM*ND];
__device__ float g_k   [NM*ND];
__device__ float g_v   [NM*ND];
__device__ float g_ctx [NM*ND];
__device__ float g_proj[NM*ND];

// ---------------- helpers ----------------
__device__ __forceinline__ float warpSum(float v) {
    #pragma unroll
    for (int o = 16; o; o >>= 1) v += __shfl_xor_sync(0xffffffffu, v, o);
    return v;
}
__device__ __forceinline__ float blockSum(float v) {
    __shared__ float s[8];
    __syncthreads();
    v = warpSum(v);
    if ((threadIdx.x & 31) == 0) s[threadIdx.x >> 5] = v;
    __syncthreads();
    if (threadIdx.x == 0) {
        float t = 0.f;
        #pragma unroll
        for (int i = 0; i < 8; i++) t += s[i];
        s[0] = t;
    }
    __syncthreads();
    return s[0];
}

__device__ __forceinline__ uint32_t f2tf32(float x) {
    uint32_t r;
    asm("cvt.rna.tf32.f32 %0, %1;" : "=r"(r) : "f"(x));
    return r;
}

__device__ __forceinline__ void mma_tf32(float d[4], const uint32_t a[4],
                                         const uint32_t b0, const uint32_t b1) {
    asm volatile(
        "mma.sync.aligned.m16n8k8.row.col.f32.tf32.tf32.f32 "
        "{%0,%1,%2,%3}, {%4,%5,%6,%7}, {%8,%9}, {%0,%1,%2,%3};\n"
        : "+f"(d[0]), "+f"(d[1]), "+f"(d[2]), "+f"(d[3])
        : "r"(a[0]), "r"(a[1]), "r"(a[2]), "r"(a[3]),
          "r"(b0), "r"(b1));
}

// ---------------- TF32 tensor-core GEMM (unchanged from round 3) ----------------
#define GK 768
#define GBK 32
#define SROW 36

__global__ __launch_bounds__(256)
void tf32_gemm_nt_bias(const float* __restrict__ A, const float* __restrict__ W,
                       const float* __restrict__ bias, float* __restrict__ C,
                       int M, int N)
{
    extern __shared__ uint32_t sm[];
    uint32_t* As = sm;                 // [2][128][SROW]
    uint32_t* Bs = sm + 2 * 128 * SROW;

    const int t     = threadIdx.x;
    const int warp  = t >> 5;
    const int lane  = t & 31;
    const int warpM = warp >> 1;       // 0..3
    const int warpN = warp & 1;        // 0..1
    const int cRow  = blockIdx.y * 128;
    const int cCol  = blockIdx.x * 128;

    const int ldRow = t >> 3;          // 0..31
    const int ldCol = (t & 7) * 4;     // 0,4,...,28

    const float* Ag = A + (long)(cRow + ldRow) * GK + ldCol;
    const float* Wg = W + (long)(cCol + ldRow) * GK + ldCol;

    #pragma unroll
    for (int p = 0; p < 4; p++) {
        float4 av = *(const float4*)(Ag + (long)p * 32 * GK);
        float4 wv = *(const float4*)(Wg + (long)p * 32 * GK);
        uint32_t* ap = &As[(p * 32 + ldRow) * SROW + ldCol];
        uint32_t* bp = &Bs[(p * 32 + ldRow) * SROW + ldCol];
        ap[0] = f2tf32(av.x); ap[1] = f2tf32(av.y); ap[2] = f2tf32(av.z); ap[3] = f2tf32(av.w);
        bp[0] = f2tf32(wv.x); bp[1] = f2tf32(wv.y); bp[2] = f2tf32(wv.z); bp[3] = f2tf32(wv.w);
    }
    __syncthreads();

    float acc[2][8][4];
    #pragma unroll
    for (int i = 0; i < 2; i++)
        #pragma unroll
        for (int j = 0; j < 8; j++)
            #pragma unroll
            for (int r = 0; r < 4; r++) acc[i][j][r] = 0.f;

    const int lq = lane >> 2;
    const int lr = lane & 3;

    int buf = 0;
    for (int kt = 0; kt < GK; kt += GBK) {
        const bool more = (kt + GBK) < GK;
        float4 pa[4], pb[4];
        if (more) {
            #pragma unroll
            for (int p = 0; p < 4; p++) {
                pa[p] = *(const float4*)(Ag + (long)p * 32 * GK + kt + GBK);
                pb[p] = *(const float4*)(Wg + (long)p * 32 * GK + kt + GBK);
            }
        }

        const uint32_t* Ab = As + buf * 128 * SROW;
        const uint32_t* Bb = Bs + buf * 128 * SROW;

        #pragma unroll
        for (int ks = 0; ks < 4; ks++) {
            const int k0 = ks * 8;
            uint32_t afr[2][4];
            #pragma unroll
            for (int mt = 0; mt < 2; mt++) {
                const int ar = warpM * 32 + mt * 16 + lq;
                afr[mt][0] = Ab[ar * SROW + k0 + lr];
                afr[mt][1] = Ab[(ar + 8) * SROW + k0 + lr];
                afr[mt][2] = Ab[ar * SROW + k0 + 4 + lr];
                afr[mt][3] = Ab[(ar + 8) * SROW + k0 + 4 + lr];
            }
            #pragma unroll
            for (int nt = 0; nt < 8; nt++) {
                const int br = warpN * 64 + nt * 8 + lq;
                uint32_t b0 = Bb[br * SROW + k0 + lr];
                uint32_t b1 = Bb[br * SROW + k0 + 4 + lr];
                mma_tf32(acc[0][nt], afr[0], b0, b1);
                mma_tf32(acc[1][nt], afr[1], b0, b1);
            }
        }

        if (more) {
            uint32_t* Ad = As + (buf ^ 1) * 128 * SROW;
            uint32_t* Bd = Bs + (buf ^ 1) * 128 * SROW;
            #pragma unroll
            for (int p = 0; p < 4; p++) {
                uint32_t* ap = &Ad[(p * 32 + ldRow) * SROW + ldCol];
                uint32_t* bp = &Bd[(p * 32 + ldRow) * SROW + ldCol];
                ap[0] = f2tf32(pa[p].x); ap[1] = f2tf32(pa[p].y);
                ap[2] = f2tf32(pa[p].z); ap[3] = f2tf32(pa[p].w);
                bp[0] = f2tf32(pb[p].x); bp[1] = f2tf32(pb[p].y);
                bp[2] = f2tf32(pb[p].z); bp[3] = f2tf32(pb[p].w);
            }
            __syncthreads();
            buf ^= 1;
        }
    }

    #pragma unroll
    for (int nt = 0; nt < 8; nt++) {
        const int col = cCol + warpN * 64 + nt * 8 + lr * 2;
        const float2 bb = *(const float2*)(bias + col);
        #pragma unroll
        for (int mt = 0; mt < 2; mt++) {
            const int row = cRow + warpM * 32 + mt * 16 + lq;
            float2 r0 = make_float2(acc[mt][nt][0] + bb.x, acc[mt][nt][1] + bb.y);
            float2 r1 = make_float2(acc[mt][nt][2] + bb.x, acc[mt][nt][3] + bb.y);
            *(float2*)(C + (long)row * N + col)       = r0;
            *(float2*)(C + (long)(row + 8) * N + col) = r1;
        }
    }
}

// ---------------- TF32 tensor-core flash attention ----------------
// Block = 128 q-rows of one (b,h). 8 warps, warp w owns rows [16w, 16w+16).
// S = Q@K^T via m16n8k8 (K natural layout = .col B operand);
// softmax on fragments; P -> SMEM (tf32) -> A-fragments; O += P@V with
// V stored transposed [d][key]. l summed from tf32-rounded p for consistency.
#define FSTR 68   // smem row stride (words); 68 % 32 == 4 -> conflict-free frags

__global__ __launch_bounds__(256, 2)
void flash_tc_kernel(const float* __restrict__ Q, const float* __restrict__ Kx,
                     const float* __restrict__ Vx, const float* __restrict__ mask,
                     const float* __restrict__ head_mask, float* __restrict__ Cx)
{
    extern __shared__ uint32_t fsm[];
    uint32_t* Qs = fsm;                  // [128][FSTR]
    uint32_t* Ks = Qs + 128 * FSTR;      // [64][FSTR]   K natural [key][d]
    uint32_t* Vs = Ks + 64 * FSTR;       // [64][FSTR]   V transposed [d][key]
    uint32_t* Ps = Vs + 64 * FSTR;       // [128][FSTR]

    const int bh = blockIdx.y;
    const int b  = bh / NH;
    const int h  = bh % NH;
    const int q0 = blockIdx.x * 128;
    const int t  = threadIdx.x;
    const int warp = t >> 5, lane = t & 31;
    const int lq = lane >> 2, lr = lane & 3;
    const int qrow = warp * 16;

    const float* Qg = Q  + (long)b * NS * ND + (long)h * NHD;
    const float* Kg = Kx + (long)b * NS * ND + (long)h * NHD;
    const float* Vg = Vx + (long)b * NS * ND + (long)h * NHD;

    // Load Q tile [128 x 64] as tf32, natural layout
    {
        const int r = t >> 1;
        const int dbase = (t & 1) * 32;
        #pragma unroll
        for (int i = 0; i < 8; i++) {
            int d0 = dbase + i * 4;
            float4 qv = *(const float4*)(Qg + (long)(q0 + r) * ND + d0);
            uint4 u = make_uint4(f2tf32(qv.x), f2tf32(qv.y), f2tf32(qv.z), f2tf32(qv.w));
            *(uint4*)&Qs[r * FSTR + d0] = u;
        }
    }

    float acc_o[8][4];
    #pragma unroll
    for (int nt = 0; nt < 8; nt++)
        #pragma unroll
        for (int j = 0; j < 4; j++) acc_o[nt][j] = 0.f;
    float m0 = -3.4e38f, m1 = -3.4e38f, l0 = 0.f, l1 = 0.f;

    for (int k0 = 0; k0 < NS; k0 += 64) {
        __syncthreads();   // protect Ks/Vs overwrite vs previous tile's reads

        // Load K (natural) and V (transposed) tiles as tf32
        {
            const int r = t >> 2;             // key 0..63
            const int dbase = (t & 3) * 16;
            #pragma unroll
            for (int i = 0; i < 4; i++) {
                int d0 = dbase + i * 4;
                float4 kv = *(const float4*)(Kg + (long)(k0 + r) * ND + d0);
                uint4 u = make_uint4(f2tf32(kv.x), f2tf32(kv.y), f2tf32(kv.z), f2tf32(kv.w));
                *(uint4*)&Ks[r * FSTR + d0] = u;
                float4 vv = *(const float4*)(Vg + (long)(k0 + r) * ND + d0);
                Vs[(d0 + 0) * FSTR + r] = f2tf32(vv.x);
                Vs[(d0 + 1) * FSTR + r] = f2tf32(vv.y);
                Vs[(d0 + 2) * FSTR + r] = f2tf32(vv.z);
                Vs[(d0 + 3) * FSTR + r] = f2tf32(vv.w);
            }
        }
        __syncthreads();

        // ---- S = Q @ K^T (16 x 64 per warp) ----
        float acc_s[8][4];
        #pragma unroll
        for (int nt = 0; nt < 8; nt++)
            #pragma unroll
            for (int j = 0; j < 4; j++) acc_s[nt][j] = 0.f;

        #pragma unroll
        for (int ks = 0; ks < 8; ks++) {
            const int kk = ks * 8;
            uint32_t a[4];
            a[0] = Qs[(qrow + lq) * FSTR + kk + lr];
            a[1] = Qs[(qrow + lq + 8) * FSTR + kk + lr];
            a[2] = Qs[(qrow + lq) * FSTR + kk + 4 + lr];
            a[3] = Qs[(qrow + lq + 8) * FSTR + kk + 4 + lr];
            #pragma unroll
            for (int nt = 0; nt < 8; nt++) {
                uint32_t b0 = Ks[(nt * 8 + lq) * FSTR + kk + lr];
                uint32_t b1 = Ks[(nt * 8 + lq) * FSTR + kk + 4 + lr];
                mma_tf32(acc_s[nt], a, b0, b1);
            }
        }

        // ---- scale + mask + online softmax ----
        float mx0 = -3.4e38f, mx1 = -3.4e38f;
        #pragma unroll
        for (int nt = 0; nt < 8; nt++) {
            float2 mk = *(const float2*)(mask + b * NS + k0 + nt * 8 + lr * 2);
            acc_s[nt][0] = fmaf(acc_s[nt][0], 0.125f, mk.x);
            acc_s[nt][1] = fmaf(acc_s[nt][1], 0.125f, mk.y);
            acc_s[nt][2] = fmaf(acc_s[nt][2], 0.125f, mk.x);
            acc_s[nt][3] = fmaf(acc_s[nt][3], 0.125f, mk.y);
            mx0 = fmaxf(mx0, fmaxf(acc_s[nt][0], acc_s[nt][1]));
            mx1 = fmaxf(mx1, fmaxf(acc_s[nt][2], acc_s[nt][3]));
        }
        mx0 = fmaxf(mx0, __shfl_xor_sync(0xffffffffu, mx0, 1));
        mx0 = fmaxf(mx0, __shfl_xor_sync(0xffffffffu, mx0, 2));
        mx1 = fmaxf(mx1, __shfl_xor_sync(0xffffffffu, mx1, 1));
        mx1 = fmaxf(mx1, __shfl_xor_sync(0xffffffffu, mx1, 2));

        const float mn0 = fmaxf(m0, mx0);
        const float mn1 = fmaxf(m1, mx1);
        const float corr0 = __expf(m0 - mn0);
        const float corr1 = __expf(m1 - mn1);
        m0 = mn0; m1 = mn1;

        float ls0 = 0.f, ls1 = 0.f;
        #pragma unroll
        for (int nt = 0; nt < 8; nt++) {
            uint32_t p00 = f2tf32(__expf(acc_s[nt][0] - mn0));
            uint32_t p01 = f2tf32(__expf(acc_s[nt][1] - mn0));
            uint32_t p10 = f2tf32(__expf(acc_s[nt][2] - mn1));
            uint32_t p11 = f2tf32(__expf(acc_s[nt][3] - mn1));
            ls0 += __uint_as_float(p00) + __uint_as_float(p01);
            ls1 += __uint_as_float(p10) + __uint_as_float(p11);
            *(uint2*)&Ps[(qrow + lq) * FSTR + nt * 8 + lr * 2]     = make_uint2(p00, p01);
            *(uint2*)&Ps[(qrow + lq + 8) * FSTR + nt * 8 + lr * 2] = make_uint2(p10, p11);
        }
        ls0 += __shfl_xor_sync(0xffffffffu, ls0, 1);
        ls0 += __shfl_xor_sync(0xffffffffu, ls0, 2);
        ls1 += __shfl_xor_sync(0xffffffffu, ls1, 1);
        ls1 += __shfl_xor_sync(0xffffffffu, ls1, 2);
        l0 = l0 * corr0 + ls0;
        l1 = l1 * corr1 + ls1;

        #pragma unroll
        for (int nt = 0; nt < 8; nt++) {
            acc_o[nt][0] *= corr0;
            acc_o[nt][1] *= corr0;
            acc_o[nt][2] *= corr1;
            acc_o[nt][3] *= corr1;
        }
        __syncwarp();   // Ps STS -> LDS (cross-lane within warp)

        // ---- O += P @ V (V^T layout: b-frag rows are d) ----
        #pragma unroll
        for (int ks = 0; ks < 8; ks++) {
            const int kk = ks * 8;
            uint32_t a[4];
            a[0] = Ps[(qrow + lq) * FSTR + kk + lr];
            a[1] = Ps[(qrow + lq + 8) * FSTR + kk + lr];
            a[2] = Ps[(qrow + lq) * FSTR + kk + 4 + lr];
            a[3] = Ps[(qrow + lq + 8) * FSTR + kk + 4 + lr];
            #pragma unroll
            for (int nt = 0; nt < 8; nt++) {
                uint32_t b0 = Vs[(nt * 8 + lq) * FSTR + kk + lr];
                uint32_t b1 = Vs[(nt * 8 + lq) * FSTR + kk + 4 + lr];
                mma_tf32(acc_o[nt], a, b0, b1);
            }
        }
    }

    // ---- epilogue: normalize, head_mask, write ctx ----
    const float hm = head_mask[h];
    const float inv0 = hm / l0;
    const float inv1 = hm / l1;
    #pragma unroll
    for (int nt = 0; nt < 8; nt++) {
        const int col = h * NHD + nt * 8 + lr * 2;
        const long r0 = (long)b * NS + q0 + qrow + lq;
        *(float2*)(Cx + r0 * ND + col) =
            make_float2(acc_o[nt][0] * inv0, acc_o[nt][1] * inv0);
        *(float2*)(Cx + (r0 + 8) * ND + col) =
            make_float2(acc_o[nt][2] * inv1, acc_o[nt][3] * inv1);
    }
}

// ---------------- residual + LayerNorm ----------------
__global__ __launch_bounds__(256)
void ln_kernel(const float* __restrict__ proj, const float* __restrict__ hidden,
               const float* __restrict__ gamma, const float* __restrict__ beta,
               float* __restrict__ out)
{
    const long row = blockIdx.x;
    const int t = threadIdx.x;
    float x[3];
    #pragma unroll
    for (int k = 0; k < 3; k++) {
        long idx = row * ND + t + k * 256;
        x[k] = proj[idx] + hidden[idx];
    }
    float s = x[0] + x[1] + x[2];
    float mu = blockSum(s) * (1.0f / ND);
    float vs = 0.f;
    #pragma unroll
    for (int k = 0; k < 3; k++) { float d = x[k] - mu; vs += d * d; }
    float var = blockSum(vs) * (1.0f / ND);
    float rstd = rsqrtf(var + 1e-12f);
    #pragma unroll
    for (int k = 0; k < 3; k++) {
        int c = t + k * 256;
        out[row * ND + c] = (x[k] - mu) * rstd * gamma[c] + beta[c];
    }
}

// ---------------- launch ----------------
extern "C" void kernel_launch(void* const* d_in, const int* in_sizes, int n_in,
                              void* d_out, int out_size)
{
    const float* hidden    = (const float*)d_in[0];
    const float* attn_mask = (const float*)d_in[1];
    const float* head_mask = (const float*)d_in[2];
    const float* Wq = (const float*)d_in[3];
    const float* bq = (const float*)d_in[4];
    const float* Wk = (const float*)d_in[5];
    const float* bk = (const float*)d_in[6];
    const float* Wv = (const float*)d_in[7];
    const float* bv = (const float*)d_in[8];
    const float* Wo = (const float*)d_in[9];
    const float* bo = (const float*)d_in[10];
    const float* gamma = (const float*)d_in[11];
    const float* beta  = (const float*)d_in[12];
    float* out = (float*)d_out;

    void *pq, *pk, *pv, *pc, *pp;
    cudaGetSymbolAddress(&pq, g_q);
    cudaGetSymbolAddress(&pk, g_k);
    cudaGetSymbolAddress(&pv, g_v);
    cudaGetSymbolAddress(&pc, g_ctx);
    cudaGetSymbolAddress(&pp, g_proj);
    float* q  = (float*)pq;
    float* k  = (float*)pk;
    float* v  = (float*)pv;
    float* cx = (float*)pc;
    float* pr = (float*)pp;

    const int FLASH_SMEM = (128*FSTR + 64*FSTR + 64*FSTR + 128*FSTR) * 4;  // 104448 B
    const int GEMM_SMEM  = 4 * 128 * SROW * 4;                             // 73728 B
    static int attr_set = 0;
    if (!attr_set) {
        cudaFuncSetAttribute(flash_tc_kernel,
                             cudaFuncAttributeMaxDynamicSharedMemorySize, FLASH_SMEM);
        cudaFuncSetAttribute(tf32_gemm_nt_bias,
                             cudaFuncAttributeMaxDynamicSharedMemorySize, GEMM_SMEM);
        attr_set = 1;
    }

    dim3 gGemm(ND / 128, NM / 128);   // (6, 64)
    tf32_gemm_nt_bias<<<gGemm, 256, GEMM_SMEM>>>(hidden, Wq, bq, q, NM, ND);
    tf32_gemm_nt_bias<<<gGemm, 256, GEMM_SMEM>>>(hidden, Wk, bk, k, NM, ND);
    tf32_gemm_nt_bias<<<gGemm, 256, GEMM_SMEM>>>(hidden, Wv, bv, v, NM, ND);

    dim3 gF(NS / 128, NBH);           // (8, 96)
    flash_tc_kernel<<<gF, 256, FLASH_SMEM>>>(q, k, v, attn_mask, head_mask, cx);

    tf32_gemm_nt_bias<<<gGemm, 256, GEMM_SMEM>>>(cx, Wo, bo, pr, NM, ND);

    ln_kernel<<<NM, 256>>>(pr, hidden, gamma, beta, out);
}

// round 5
// speedup vs baseline: 3.8214x; 1.0741x over previous
#include <cuda_runtime.h>
#include <math.h>
#include <stdint.h>

// Problem constants
#define NB 8
#define NS 1024
#define ND 768
#define NH 12
#define NHD 64
#define NM (NB*NS)        // 8192 rows
#define NBH (NB*NH)       // 96 batch-head pairs

// ---------------- scratch (static device globals; no allocation) ----------------
__device__ float g_q   [NM*ND];
__device__ float g_k   [NM*ND];
__device__ float g_v   [NM*ND];
__device__ float g_ctx [NM*ND];
__device__ float g_proj[NM*ND];

// ---------------- helpers ----------------
__device__ __forceinline__ float warpSum(float v) {
    #pragma unroll
    for (int o = 16; o; o >>= 1) v += __shfl_xor_sync(0xffffffffu, v, o);
    return v;
}
__device__ __forceinline__ float blockSum(float v) {
    __shared__ float s[8];
    __syncthreads();
    v = warpSum(v);
    if ((threadIdx.x & 31) == 0) s[threadIdx.x >> 5] = v;
    __syncthreads();
    if (threadIdx.x == 0) {
        float t = 0.f;
        #pragma unroll
        for (int i = 0; i < 8; i++) t += s[i];
        s[0] = t;
    }
    __syncthreads();
    return s[0];
}

__device__ __forceinline__ uint32_t f2tf32(float x) {
    uint32_t r;
    asm("cvt.rna.tf32.f32 %0, %1;" : "=r"(r) : "f"(x));
    return r;
}

__device__ __forceinline__ void mma_tf32(float d[4], const uint32_t a[4],
                                         const uint32_t b0, const uint32_t b1) {
    asm volatile(
        "mma.sync.aligned.m16n8k8.row.col.f32.tf32.tf32.f32 "
        "{%0,%1,%2,%3}, {%4,%5,%6,%7}, {%8,%9}, {%0,%1,%2,%3};\n"
        : "+f"(d[0]), "+f"(d[1]), "+f"(d[2]), "+f"(d[3])
        : "r"(a[0]), "r"(a[1]), "r"(a[2]), "r"(a[3]),
          "r"(b0), "r"(b1));
}

// ldmatrix x4 (b16 path moves raw 32-bit tf32 words; distribution matches
// mma fragment layout when given the right per-lane row addresses).
__device__ __forceinline__ void ldsm_x4(uint32_t r[4], uint32_t saddr) {
    asm volatile("ldmatrix.sync.aligned.m8n8.x4.shared.b16 {%0,%1,%2,%3}, [%4];"
                 : "=r"(r[0]), "=r"(r[1]), "=r"(r[2]), "=r"(r[3]) : "r"(saddr));
}

// Per-lane byte offsets (word stride STR) for fragment ldmatrix:
// A-pattern (x4 -> a0,a1,a2,a3 of one 16-row tile):
//   lanes 0-7: rows 0-7 blk0 | 8-15: rows 8-15 blk0 | 16-23: rows 0-7 blk1 | 24-31: rows 8-15 blk1
__device__ __forceinline__ uint32_t ldsm_a_off(int lane, int STR) {
    return (uint32_t)((((lane & 15) * STR + ((lane >> 2) & 4)) << 2));
}
// B-pattern (x4 -> b0,b1 of n-tile nt and nt+1):
//   lanes 0-7: rows 0-7 blk0 | 8-15: rows 0-7 blk1 | 16-23: rows 8-15 blk0 | 24-31: rows 8-15 blk1
__device__ __forceinline__ uint32_t ldsm_b_off(int lane, int STR) {
    return (uint32_t)(((((lane & 7) + ((lane >> 1) & 8)) * STR + ((lane >> 1) & 4)) << 2));
}

// ---------------- TF32 tensor-core GEMM ----------------
#define GK 768
#define GBK 32
#define SROW 36

__global__ __launch_bounds__(256)
void tf32_gemm_nt_bias(const float* __restrict__ A, const float* __restrict__ W,
                       const float* __restrict__ bias, float* __restrict__ C,
                       int M, int N)
{
    extern __shared__ uint32_t sm[];
    uint32_t* As = sm;                 // [2][128][SROW]
    uint32_t* Bs = sm + 2 * 128 * SROW;

    const int t     = threadIdx.x;
    const int warp  = t >> 5;
    const int lane  = t & 31;
    const int warpM = warp >> 1;       // 0..3
    const int warpN = warp & 1;        // 0..1
    const int cRow  = blockIdx.y * 128;
    const int cCol  = blockIdx.x * 128;

    const int ldRow = t >> 3;          // 0..31
    const int ldCol = (t & 7) * 4;     // 0,4,...,28

    const float* Ag = A + (long)(cRow + ldRow) * GK + ldCol;
    const float* Wg = W + (long)(cCol + ldRow) * GK + ldCol;

    #pragma unroll
    for (int p = 0; p < 4; p++) {
        float4 av = *(const float4*)(Ag + (long)p * 32 * GK);
        float4 wv = *(const float4*)(Wg + (long)p * 32 * GK);
        uint32_t* ap = &As[(p * 32 + ldRow) * SROW + ldCol];
        uint32_t* bp = &Bs[(p * 32 + ldRow) * SROW + ldCol];
        ap[0] = f2tf32(av.x); ap[1] = f2tf32(av.y); ap[2] = f2tf32(av.z); ap[3] = f2tf32(av.w);
        bp[0] = f2tf32(wv.x); bp[1] = f2tf32(wv.y); bp[2] = f2tf32(wv.z); bp[3] = f2tf32(wv.w);
    }
    __syncthreads();

    float acc[2][8][4];
    #pragma unroll
    for (int i = 0; i < 2; i++)
        #pragma unroll
        for (int j = 0; j < 8; j++)
            #pragma unroll
            for (int r = 0; r < 4; r++) acc[i][j][r] = 0.f;

    const int lq = lane >> 2;
    const int lr = lane & 3;

    // ldmatrix base addresses (byte offsets into dynamic smem)
    const uint32_t sb = (uint32_t)__cvta_generic_to_shared(sm);
    const uint32_t aoff = ldsm_a_off(lane, SROW);
    const uint32_t boff = ldsm_b_off(lane, SROW);
    const uint32_t BUFB = 128 * SROW * 4;          // bytes per buffer
    const uint32_t aA0 = sb + (uint32_t)(((warpM * 32) * SROW) << 2) + aoff;
    const uint32_t aA1 = aA0 + (uint32_t)((16 * SROW) << 2);
    const uint32_t bB0 = sb + 2 * BUFB + (uint32_t)(((warpN * 64) * SROW) << 2) + boff;

    int buf = 0;
    for (int kt = 0; kt < GK; kt += GBK) {
        const bool more = (kt + GBK) < GK;
        float4 pa[4], pb[4];
        if (more) {
            #pragma unroll
            for (int p = 0; p < 4; p++) {
                pa[p] = *(const float4*)(Ag + (long)p * 32 * GK + kt + GBK);
                pb[p] = *(const float4*)(Wg + (long)p * 32 * GK + kt + GBK);
            }
        }

        const uint32_t abuf = aA0 + buf * BUFB;
        const uint32_t abuf1 = aA1 + buf * BUFB;
        const uint32_t bbuf = bB0 + buf * BUFB;

        #pragma unroll
        for (int ks = 0; ks < 4; ks++) {
            uint32_t afr0[4], afr1[4];
            ldsm_x4(afr0, abuf  + ks * 32);
            ldsm_x4(afr1, abuf1 + ks * 32);
            #pragma unroll
            for (int nt2 = 0; nt2 < 4; nt2++) {
                uint32_t bb[4];
                ldsm_x4(bb, bbuf + nt2 * ((16 * SROW) << 2) + ks * 32);
                mma_tf32(acc[0][nt2 * 2],     afr0, bb[0], bb[1]);
                mma_tf32(acc[0][nt2 * 2 + 1], afr0, bb[2], bb[3]);
                mma_tf32(acc[1][nt2 * 2],     afr1, bb[0], bb[1]);
                mma_tf32(acc[1][nt2 * 2 + 1], afr1, bb[2], bb[3]);
            }
        }

        if (more) {
            uint32_t* Ad = As + (buf ^ 1) * 128 * SROW;
            uint32_t* Bd = Bs + (buf ^ 1) * 128 * SROW;
            #pragma unroll
            for (int p = 0; p < 4; p++) {
                uint32_t* ap = &Ad[(p * 32 + ldRow) * SROW + ldCol];
                uint32_t* bp = &Bd[(p * 32 + ldRow) * SROW + ldCol];
                ap[0] = f2tf32(pa[p].x); ap[1] = f2tf32(pa[p].y);
                ap[2] = f2tf32(pa[p].z); ap[3] = f2tf32(pa[p].w);
                bp[0] = f2tf32(pb[p].x); bp[1] = f2tf32(pb[p].y);
                bp[2] = f2tf32(pb[p].z); bp[3] = f2tf32(pb[p].w);
            }
            __syncthreads();
            buf ^= 1;
        }
    }

    #pragma unroll
    for (int nt = 0; nt < 8; nt++) {
        const int col = cCol + warpN * 64 + nt * 8 + lr * 2;
        const float2 bb = *(const float2*)(bias + col);
        #pragma unroll
        for (int mt = 0; mt < 2; mt++) {
            const int row = cRow + warpM * 32 + mt * 16 + lq;
            float2 r0 = make_float2(acc[mt][nt][0] + bb.x, acc[mt][nt][1] + bb.y);
            float2 r1 = make_float2(acc[mt][nt][2] + bb.x, acc[mt][nt][3] + bb.y);
            *(float2*)(C + (long)row * N + col)       = r0;
            *(float2*)(C + (long)(row + 8) * N + col) = r1;
        }
    }
}

// ---------------- TF32 tensor-core flash attention (ldmatrix fragments) ----------------
#define FSTR 68   // 68 % 32 == 4 -> ldmatrix row starts hit distinct bank quads

__global__ __launch_bounds__(256, 2)
void flash_tc_kernel(const float* __restrict__ Q, const float* __restrict__ Kx,
                     const float* __restrict__ Vx, const float* __restrict__ mask,
                     const float* __restrict__ head_mask, float* __restrict__ Cx)
{
    extern __shared__ uint32_t fsm[];
    uint32_t* Qs = fsm;                     // [128][FSTR]  Q natural [row][d]
    uint32_t* Ks = Qs + 128 * FSTR;         // [64][FSTR]   K natural [key][d]
    uint32_t* Vs = Ks + 64 * FSTR;          // [64][FSTR]   V transposed [d][key]
    uint32_t* Ps = Vs + 64 * FSTR;          // [128][FSTR]  P natural [row][key]
    float*    Ms = (float*)(Ps + 128 * FSTR);  // [1024] mask row

    const int bh = blockIdx.y;
    const int b  = bh / NH;
    const int h  = bh % NH;
    const int q0 = blockIdx.x * 128;
    const int t  = threadIdx.x;
    const int warp = t >> 5, lane = t & 31;
    const int lq = lane >> 2, lr = lane & 3;
    const int qrow = warp * 16;

    const float* Qg = Q  + (long)b * NS * ND + (long)h * NHD;
    const float* Kg = Kx + (long)b * NS * ND + (long)h * NHD;
    const float* Vg = Vx + (long)b * NS * ND + (long)h * NHD;

    // Load Q tile [128 x 64] as tf32 (natural) + mask row into SMEM
    {
        const int r = t >> 1;
        const int dbase = (t & 1) * 32;
        #pragma unroll
        for (int i = 0; i < 8; i++) {
            int d0 = dbase + i * 4;
            float4 qv = *(const float4*)(Qg + (long)(q0 + r) * ND + d0);
            uint4 u = make_uint4(f2tf32(qv.x), f2tf32(qv.y), f2tf32(qv.z), f2tf32(qv.w));
            *(uint4*)&Qs[r * FSTR + d0] = u;
        }
        *(float4*)&Ms[t * 4] = *(const float4*)(mask + b * NS + t * 4);
    }

    // ldmatrix lane addresses
    const uint32_t sb = (uint32_t)__cvta_generic_to_shared(fsm);
    const uint32_t aoff = ldsm_a_off(lane, FSTR);
    const uint32_t boff = ldsm_b_off(lane, FSTR);
    const uint32_t qA = sb + (uint32_t)((qrow * FSTR) << 2) + aoff;
    const uint32_t kB = sb + (uint32_t)((128 * FSTR) << 2) + boff;
    const uint32_t vB = sb + (uint32_t)((192 * FSTR) << 2) + boff;
    const uint32_t pA = sb + (uint32_t)(((256 + qrow) * FSTR) << 2) + aoff;
    const uint32_t NT2STEP = (uint32_t)((16 * FSTR) << 2);

    float acc_o[8][4];
    #pragma unroll
    for (int nt = 0; nt < 8; nt++)
        #pragma unroll
        for (int j = 0; j < 4; j++) acc_o[nt][j] = 0.f;
    float m0 = -3.4e38f, m1 = -3.4e38f, l0 = 0.f, l1 = 0.f;

    for (int k0 = 0; k0 < NS; k0 += 64) {
        __syncthreads();   // protect Ks/Vs overwrite vs previous tile's reads

        // Load K (natural) and V (transposed) tiles as tf32
        {
            const int r = t >> 2;             // key 0..63
            const int dbase = (t & 3) * 16;
            #pragma unroll
            for (int i = 0; i < 4; i++) {
                int d0 = dbase + i * 4;
                float4 kv = *(const float4*)(Kg + (long)(k0 + r) * ND + d0);
                uint4 u = make_uint4(f2tf32(kv.x), f2tf32(kv.y), f2tf32(kv.z), f2tf32(kv.w));
                *(uint4*)&Ks[r * FSTR + d0] = u;
                float4 vv = *(const float4*)(Vg + (long)(k0 + r) * ND + d0);
                Vs[(d0 + 0) * FSTR + r] = f2tf32(vv.x);
                Vs[(d0 + 1) * FSTR + r] = f2tf32(vv.y);
                Vs[(d0 + 2) * FSTR + r] = f2tf32(vv.z);
                Vs[(d0 + 3) * FSTR + r] = f2tf32(vv.w);
            }
        }
        __syncthreads();

        // ---- S = Q @ K^T (16 x 64 per warp) ----
        float acc_s[8][4];
        #pragma unroll
        for (int nt = 0; nt < 8; nt++)
            #pragma unroll
            for (int j = 0; j < 4; j++) acc_s[nt][j] = 0.f;

        #pragma unroll
        for (int ks = 0; ks < 8; ks++) {
            uint32_t a[4];
            ldsm_x4(a, qA + ks * 32);
            #pragma unroll
            for (int nt2 = 0; nt2 < 4; nt2++) {
                uint32_t bb[4];
                ldsm_x4(bb, kB + nt2 * NT2STEP + ks * 32);
                mma_tf32(acc_s[nt2 * 2],     a, bb[0], bb[1]);
                mma_tf32(acc_s[nt2 * 2 + 1], a, bb[2], bb[3]);
            }
        }

        // ---- scale + mask + online softmax ----
        float mx0 = -3.4e38f, mx1 = -3.4e38f;
        #pragma unroll
        for (int nt = 0; nt < 8; nt++) {
            float2 mk = *(const float2*)&Ms[k0 + nt * 8 + lr * 2];
            acc_s[nt][0] = fmaf(acc_s[nt][0], 0.125f, mk.x);
            acc_s[nt][1] = fmaf(acc_s[nt][1], 0.125f, mk.y);
            acc_s[nt][2] = fmaf(acc_s[nt][2], 0.125f, mk.x);
            acc_s[nt][3] = fmaf(acc_s[nt][3], 0.125f, mk.y);
            mx0 = fmaxf(mx0, fmaxf(acc_s[nt][0], acc_s[nt][1]));
            mx1 = fmaxf(mx1, fmaxf(acc_s[nt][2], acc_s[nt][3]));
        }
        mx0 = fmaxf(mx0, __shfl_xor_sync(0xffffffffu, mx0, 1));
        mx0 = fmaxf(mx0, __shfl_xor_sync(0xffffffffu, mx0, 2));
        mx1 = fmaxf(mx1, __shfl_xor_sync(0xffffffffu, mx1, 1));
        mx1 = fmaxf(mx1, __shfl_xor_sync(0xffffffffu, mx1, 2));

        const float mn0 = fmaxf(m0, mx0);
        const float mn1 = fmaxf(m1, mx1);
        const float corr0 = __expf(m0 - mn0);
        const float corr1 = __expf(m1 - mn1);
        m0 = mn0; m1 = mn1;

        float ls0 = 0.f, ls1 = 0.f;
        #pragma unroll
        for (int nt = 0; nt < 8; nt++) {
            uint32_t p00 = f2tf32(__expf(acc_s[nt][0] - mn0));
            uint32_t p01 = f2tf32(__expf(acc_s[nt][1] - mn0));
            uint32_t p10 = f2tf32(__expf(acc_s[nt][2] - mn1));
            uint32_t p11 = f2tf32(__expf(acc_s[nt][3] - mn1));
            ls0 += __uint_as_float(p00) + __uint_as_float(p01);
            ls1 += __uint_as_float(p10) + __uint_as_float(p11);
            *(uint2*)&Ps[(qrow + lq) * FSTR + nt * 8 + lr * 2]     = make_uint2(p00, p01);
            *(uint2*)&Ps[(qrow + lq + 8) * FSTR + nt * 8 + lr * 2] = make_uint2(p10, p11);
        }
        ls0 += __shfl_xor_sync(0xffffffffu, ls0, 1);
        ls0 += __shfl_xor_sync(0xffffffffu, ls0, 2);
        ls1 += __shfl_xor_sync(0xffffffffu, ls1, 1);
        ls1 += __shfl_xor_sync(0xffffffffu, ls1, 2);
        l0 = l0 * corr0 + ls0;
        l1 = l1 * corr1 + ls1;

        #pragma unroll
        for (int nt = 0; nt < 8; nt++) {
            acc_o[nt][0] *= corr0;
            acc_o[nt][1] *= corr0;
            acc_o[nt][2] *= corr1;
            acc_o[nt][3] *= corr1;
        }
        __syncwarp();   // Ps STS -> LDSM (cross-lane within warp)

        // ---- O += P @ V ----
        #pragma unroll
        for (int ks = 0; ks < 8; ks++) {
            uint32_t a[4];
            ldsm_x4(a, pA + ks * 32);
            #pragma unroll
            for (int nt2 = 0; nt2 < 4; nt2++) {
                uint32_t bb[4];
                ldsm_x4(bb, vB + nt2 * NT2STEP + ks * 32);
                mma_tf32(acc_o[nt2 * 2],     a, bb[0], bb[1]);
                mma_tf32(acc_o[nt2 * 2 + 1], a, bb[2], bb[3]);
            }
        }
    }

    // ---- epilogue: normalize, head_mask, write ctx ----
    const float hm = head_mask[h];
    const float inv0 = hm / l0;
    const float inv1 = hm / l1;
    #pragma unroll
    for (int nt = 0; nt < 8; nt++) {
        const int col = h * NHD + nt * 8 + lr * 2;
        const long r0 = (long)b * NS + q0 + qrow + lq;
        *(float2*)(Cx + r0 * ND + col) =
            make_float2(acc_o[nt][0] * inv0, acc_o[nt][1] * inv0);
        *(float2*)(Cx + (r0 + 8) * ND + col) =
            make_float2(acc_o[nt][2] * inv1, acc_o[nt][3] * inv1);
    }
}

// ---------------- residual + LayerNorm ----------------
__global__ __launch_bounds__(256)
void ln_kernel(const float* __restrict__ proj, const float* __restrict__ hidden,
               const float* __restrict__ gamma, const float* __restrict__ beta,
               float* __restrict__ out)
{
    const long row = blockIdx.x;
    const int t = threadIdx.x;
    float x[3];
    #pragma unroll
    for (int k = 0; k < 3; k++) {
        long idx = row * ND + t + k * 256;
        x[k] = proj[idx] + hidden[idx];
    }
    float s = x[0] + x[1] + x[2];
    float mu = blockSum(s) * (1.0f / ND);
    float vs = 0.f;
    #pragma unroll
    for (int k = 0; k < 3; k++) { float d = x[k] - mu; vs += d * d; }
    float var = blockSum(vs) * (1.0f / ND);
    float rstd = rsqrtf(var + 1e-12f);
    #pragma unroll
    for (int k = 0; k < 3; k++) {
        int c = t + k * 256;
        out[row * ND + c] = (x[k] - mu) * rstd * gamma[c] + beta[c];
    }
}

// ---------------- launch ----------------
extern "C" void kernel_launch(void* const* d_in, const int* in_sizes, int n_in,
                              void* d_out, int out_size)
{
    const float* hidden    = (const float*)d_in[0];
    const float* attn_mask = (const float*)d_in[1];
    const float* head_mask = (const float*)d_in[2];
    const float* Wq = (const float*)d_in[3];
    const float* bq = (const float*)d_in[4];
    const float* Wk = (const float*)d_in[5];
    const float* bk = (const float*)d_in[6];
    const float* Wv = (const float*)d_in[7];
    const float* bv = (const float*)d_in[8];
    const float* Wo = (const float*)d_in[9];
    const float* bo = (const float*)d_in[10];
    const float* gamma = (const float*)d_in[11];
    const float* beta  = (const float*)d_in[12];
    float* out = (float*)d_out;

    void *pq, *pk, *pv, *pc, *pp;
    cudaGetSymbolAddress(&pq, g_q);
    cudaGetSymbolAddress(&pk, g_k);
    cudaGetSymbolAddress(&pv, g_v);
    cudaGetSymbolAddress(&pc, g_ctx);
    cudaGetSymbolAddress(&pp, g_proj);
    float* q  = (float*)pq;
    float* k  = (float*)pk;
    float* v  = (float*)pv;
    float* cx = (float*)pc;
    float* pr = (float*)pp;

    const int FLASH_SMEM = (128*FSTR + 64*FSTR + 64*FSTR + 128*FSTR) * 4 + 4096; // 108544 B
    const int GEMM_SMEM  = 4 * 128 * SROW * 4;                                   // 73728 B
    static int attr_set = 0;
    if (!attr_set) {
        cudaFuncSetAttribute(flash_tc_kernel,
                             cudaFuncAttributeMaxDynamicSharedMemorySize, FLASH_SMEM);
        cudaFuncSetAttribute(tf32_gemm_nt_bias,
                             cudaFuncAttributeMaxDynamicSharedMemorySize, GEMM_SMEM);
        attr_set = 1;
    }

    dim3 gGemm(ND / 128, NM / 128);   // (6, 64)
    tf32_gemm_nt_bias<<<gGemm, 256, GEMM_SMEM>>>(hidden, Wq, bq, q, NM, ND);
    tf32_gemm_nt_bias<<<gGemm, 256, GEMM_SMEM>>>(hidden, Wk, bk, k, NM, ND);
    tf32_gemm_nt_bias<<<gGemm, 256, GEMM_SMEM>>>(hidden, Wv, bv, v, NM, ND);

    dim3 gF(NS / 128, NBH);           // (8, 96)
    flash_tc_kernel<<<gF, 256, FLASH_SMEM>>>(q, k, v, attn_mask, head_mask, cx);

    tf32_gemm_nt_bias<<<gGemm, 256, GEMM_SMEM>>>(cx, Wo, bo, pr, NM, ND);

    ln_kernel<<<NM, 256>>>(pr, hidden, gamma, beta, out);
}

// round 6
// speedup vs baseline: 4.7589x; 1.2453x over previous
#include <cuda_runtime.h>
#include <cuda_bf16.h>
#include <math.h>
#include <stdint.h>

// Problem constants
#define NB 8
#define NS 1024
#define ND 768
#define NH 12
#define NHD 64
#define NM (NB*NS)        // 8192 rows
#define NBH (NB*NH)       // 96 batch-head pairs

// ---------------- scratch (static device globals; no allocation) ----------------
__device__ float g_q   [NM*ND];
__device__ float g_k   [NM*ND];
__device__ float g_v   [NM*ND];
__device__ float g_ctx [NM*ND];
__device__ float g_proj[NM*ND];

// ---------------- helpers ----------------
__device__ __forceinline__ float warpSum(float v) {
    #pragma unroll
    for (int o = 16; o; o >>= 1) v += __shfl_xor_sync(0xffffffffu, v, o);
    return v;
}
__device__ __forceinline__ float blockSum(float v) {
    __shared__ float s[8];
    __syncthreads();
    v = warpSum(v);
    if ((threadIdx.x & 31) == 0) s[threadIdx.x >> 5] = v;
    __syncthreads();
    if (threadIdx.x == 0) {
        float t = 0.f;
        #pragma unroll
        for (int i = 0; i < 8; i++) t += s[i];
        s[0] = t;
    }
    __syncthreads();
    return s[0];
}

__device__ __forceinline__ uint32_t f2tf32(float x) {
    uint32_t r;
    asm("cvt.rna.tf32.f32 %0, %1;" : "=r"(r) : "f"(x));
    return r;
}

__device__ __forceinline__ void mma_tf32(float d[4], const uint32_t a[4],
                                         const uint32_t b0, const uint32_t b1) {
    asm volatile(
        "mma.sync.aligned.m16n8k8.row.col.f32.tf32.tf32.f32 "
        "{%0,%1,%2,%3}, {%4,%5,%6,%7}, {%8,%9}, {%0,%1,%2,%3};\n"
        : "+f"(d[0]), "+f"(d[1]), "+f"(d[2]), "+f"(d[3])
        : "r"(a[0]), "r"(a[1]), "r"(a[2]), "r"(a[3]),
          "r"(b0), "r"(b1));
}

__device__ __forceinline__ void mma_bf16(float d[4], const uint32_t a[4],
                                         const uint32_t b0, const uint32_t b1) {
    asm volatile(
        "mma.sync.aligned.m16n8k16.row.col.f32.bf16.bf16.f32 "
        "{%0,%1,%2,%3}, {%4,%5,%6,%7}, {%8,%9}, {%0,%1,%2,%3};\n"
        : "+f"(d[0]), "+f"(d[1]), "+f"(d[2]), "+f"(d[3])
        : "r"(a[0]), "r"(a[1]), "r"(a[2]), "r"(a[3]),
          "r"(b0), "r"(b1));
}

__device__ __forceinline__ void ldsm_x4(uint32_t r[4], uint32_t saddr) {
    asm volatile("ldmatrix.sync.aligned.m8n8.x4.shared.b16 {%0,%1,%2,%3}, [%4];"
                 : "=r"(r[0]), "=r"(r[1]), "=r"(r[2]), "=r"(r[3]) : "r"(saddr));
}
__device__ __forceinline__ void ldsm_x4_t(uint32_t r[4], uint32_t saddr) {
    asm volatile("ldmatrix.sync.aligned.m8n8.x4.trans.shared.b16 {%0,%1,%2,%3}, [%4];"
                 : "=r"(r[0]), "=r"(r[1]), "=r"(r[2]), "=r"(r[3]) : "r"(saddr));
}

// tf32 fragment ldmatrix offsets (word stride STR) — used by the GEMM
__device__ __forceinline__ uint32_t ldsm_a_off(int lane, int STR) {
    return (uint32_t)((((lane & 15) * STR + ((lane >> 2) & 4)) << 2));
}
__device__ __forceinline__ uint32_t ldsm_b_off(int lane, int STR) {
    return (uint32_t)(((((lane & 7) + ((lane >> 1) & 8)) * STR + ((lane >> 1) & 4)) << 2));
}

__device__ __forceinline__ uint32_t pack_bf2(float lo, float hi) {
    __nv_bfloat162 p = __floats2bfloat162_rn(lo, hi);   // .x = lo (low halfword)
    return *(uint32_t*)&p;
}

// ---------------- TF32 tensor-core GEMM (unchanged from round 5) ----------------
#define GK 768
#define GBK 32
#define SROW 36

__global__ __launch_bounds__(256)
void tf32_gemm_nt_bias(const float* __restrict__ A, const float* __restrict__ W,
                       const float* __restrict__ bias, float* __restrict__ C,
                       int M, int N)
{
    extern __shared__ uint32_t sm[];
    uint32_t* As = sm;                 // [2][128][SROW]
    uint32_t* Bs = sm + 2 * 128 * SROW;

    const int t     = threadIdx.x;
    const int warp  = t >> 5;
    const int lane  = t & 31;
    const int warpM = warp >> 1;
    const int warpN = warp & 1;
    const int cRow  = blockIdx.y * 128;
    const int cCol  = blockIdx.x * 128;

    const int ldRow = t >> 3;
    const int ldCol = (t & 7) * 4;

    const float* Ag = A + (long)(cRow + ldRow) * GK + ldCol;
    const float* Wg = W + (long)(cCol + ldRow) * GK + ldCol;

    #pragma unroll
    for (int p = 0; p < 4; p++) {
        float4 av = *(const float4*)(Ag + (long)p * 32 * GK);
        float4 wv = *(const float4*)(Wg + (long)p * 32 * GK);
        uint32_t* ap = &As[(p * 32 + ldRow) * SROW + ldCol];
        uint32_t* bp = &Bs[(p * 32 + ldRow) * SROW + ldCol];
        ap[0] = f2tf32(av.x); ap[1] = f2tf32(av.y); ap[2] = f2tf32(av.z); ap[3] = f2tf32(av.w);
        bp[0] = f2tf32(wv.x); bp[1] = f2tf32(wv.y); bp[2] = f2tf32(wv.z); bp[3] = f2tf32(wv.w);
    }
    __syncthreads();

    float acc[2][8][4];
    #pragma unroll
    for (int i = 0; i < 2; i++)
        #pragma unroll
        for (int j = 0; j < 8; j++)
            #pragma unroll
            for (int r = 0; r < 4; r++) acc[i][j][r] = 0.f;

    const int lq = lane >> 2;
    const int lr = lane & 3;

    const uint32_t sb = (uint32_t)__cvta_generic_to_shared(sm);
    const uint32_t aoff = ldsm_a_off(lane, SROW);
    const uint32_t boff = ldsm_b_off(lane, SROW);
    const uint32_t BUFB = 128 * SROW * 4;
    const uint32_t aA0 = sb + (uint32_t)(((warpM * 32) * SROW) << 2) + aoff;
    const uint32_t aA1 = aA0 + (uint32_t)((16 * SROW) << 2);
    const uint32_t bB0 = sb + 2 * BUFB + (uint32_t)(((warpN * 64) * SROW) << 2) + boff;

    int buf = 0;
    for (int kt = 0; kt < GK; kt += GBK) {
        const bool more = (kt + GBK) < GK;
        float4 pa[4], pb[4];
        if (more) {
            #pragma unroll
            for (int p = 0; p < 4; p++) {
                pa[p] = *(const float4*)(Ag + (long)p * 32 * GK + kt + GBK);
                pb[p] = *(const float4*)(Wg + (long)p * 32 * GK + kt + GBK);
            }
        }

        const uint32_t abuf = aA0 + buf * BUFB;
        const uint32_t abuf1 = aA1 + buf * BUFB;
        const uint32_t bbuf = bB0 + buf * BUFB;

        #pragma unroll
        for (int ks = 0; ks < 4; ks++) {
            uint32_t afr0[4], afr1[4];
            ldsm_x4(afr0, abuf  + ks * 32);
            ldsm_x4(afr1, abuf1 + ks * 32);
            #pragma unroll
            for (int nt2 = 0; nt2 < 4; nt2++) {
                uint32_t bb[4];
                ldsm_x4(bb, bbuf + nt2 * ((16 * SROW) << 2) + ks * 32);
                mma_tf32(acc[0][nt2 * 2],     afr0, bb[0], bb[1]);
                mma_tf32(acc[0][nt2 * 2 + 1], afr0, bb[2], bb[3]);
                mma_tf32(acc[1][nt2 * 2],     afr1, bb[0], bb[1]);
                mma_tf32(acc[1][nt2 * 2 + 1], afr1, bb[2], bb[3]);
            }
        }

        if (more) {
            uint32_t* Ad = As + (buf ^ 1) * 128 * SROW;
            uint32_t* Bd = Bs + (buf ^ 1) * 128 * SROW;
            #pragma unroll
            for (int p = 0; p < 4; p++) {
                uint32_t* ap = &Ad[(p * 32 + ldRow) * SROW + ldCol];
                uint32_t* bp = &Bd[(p * 32 + ldRow) * SROW + ldCol];
                ap[0] = f2tf32(pa[p].x); ap[1] = f2tf32(pa[p].y);
                ap[2] = f2tf32(pa[p].z); ap[3] = f2tf32(pa[p].w);
                bp[0] = f2tf32(pb[p].x); bp[1] = f2tf32(pb[p].y);
                bp[2] = f2tf32(pb[p].z); bp[3] = f2tf32(pb[p].w);
            }
            __syncthreads();
            buf ^= 1;
        }
    }

    #pragma unroll
    for (int nt = 0; nt < 8; nt++) {
        const int col = cCol + warpN * 64 + nt * 8 + lr * 2;
        const float2 bb = *(const float2*)(bias + col);
        #pragma unroll
        for (int mt = 0; mt < 2; mt++) {
            const int row = cRow + warpM * 32 + mt * 16 + lq;
            float2 r0 = make_float2(acc[mt][nt][0] + bb.x, acc[mt][nt][1] + bb.y);
            float2 r1 = make_float2(acc[mt][nt][2] + bb.x, acc[mt][nt][3] + bb.y);
            *(float2*)(C + (long)row * N + col)       = r0;
            *(float2*)(C + (long)(row + 8) * N + col) = r1;
        }
    }
}

// ---------------- BF16 tensor-core flash attention ----------------
// Block = 128 q-rows of one (b,h); 8 warps, warp w owns rows [16w,16w+16).
// All tiles stored bf16 with row stride 72 halves (144 B; 144 % 128 == 16 ->
// ldmatrix 8-row groups hit distinct 16B bank quads).
// S = Q@K^T via m16n8k16 (K natural [key][d], non-trans LDSM);
// P (bf16) -> SMEM -> A-frags; O += P@V with V natural [key][d] via LDSM.trans.
#define FW 36     // row stride in 32-bit words (72 bf16)
#define ROWB 144  // row stride bytes

__global__ __launch_bounds__(256, 2)
void flash_bf16_kernel(const float* __restrict__ Q, const float* __restrict__ Kx,
                       const float* __restrict__ Vx, const float* __restrict__ mask,
                       const float* __restrict__ head_mask, float* __restrict__ Cx)
{
    extern __shared__ uint32_t fsm[];
    uint32_t* Qs = fsm;                 // [128][FW]  Q natural [row][d] bf16
    uint32_t* Ks = Qs + 128 * FW;       // [64][FW]   K natural [key][d] bf16
    uint32_t* Vs = Ks + 64 * FW;        // [64][FW]   V natural [key][d] bf16
    uint32_t* Ps = Vs + 64 * FW;        // [128][FW]  P natural [row][key] bf16
    float*    Ms = (float*)(Ps + 128 * FW);  // [1024] mask row

    const int bh = blockIdx.y;
    const int b  = bh / NH;
    const int h  = bh % NH;
    const int q0 = blockIdx.x * 128;
    const int t  = threadIdx.x;
    const int warp = t >> 5, lane = t & 31;
    const int lq = lane >> 2, lr = lane & 3;
    const int qrow = warp * 16;

    const float* Qg = Q  + (long)b * NS * ND + (long)h * NHD;
    const float* Kg = Kx + (long)b * NS * ND + (long)h * NHD;
    const float* Vg = Vx + (long)b * NS * ND + (long)h * NHD;

    // Load Q tile [128 x 64] -> bf16 natural + mask row
    {
        const int r = t >> 1;
        const int dbase = (t & 1) * 32;
        #pragma unroll
        for (int i = 0; i < 8; i++) {
            int d0 = dbase + i * 4;
            float4 qv = *(const float4*)(Qg + (long)(q0 + r) * ND + d0);
            Qs[r * FW + (d0 >> 1)]     = pack_bf2(qv.x, qv.y);
            Qs[r * FW + (d0 >> 1) + 1] = pack_bf2(qv.z, qv.w);
        }
        *(float4*)&Ms[t * 4] = *(const float4*)(mask + b * NS + t * 4);
    }

    // ldmatrix per-lane byte offsets
    const uint32_t sb = (uint32_t)__cvta_generic_to_shared(fsm);
    // A-pattern (Q, P): row = lane&15, colbyte = (lane>>4)*16
    const uint32_t aoff = (uint32_t)((lane & 15) * ROWB + ((lane >> 4) << 4));
    // K B-pattern: row = (lane&7) + (lane>>4)*8, colbyte = ((lane>>3)&1)*16
    const uint32_t koff = (uint32_t)(((lane & 7) + ((lane >> 4) << 3)) * ROWB
                                     + (((lane >> 3) & 1) << 4));
    // V trans-pattern: row = (lane&7) + ((lane>>3)&1)*8, colbyte = (lane>>4)*16
    const uint32_t voff = (uint32_t)(((lane & 7) + (((lane >> 3) & 1) << 3)) * ROWB
                                     + ((lane >> 4) << 4));

    const uint32_t qA = sb + (uint32_t)(qrow * ROWB) + aoff;
    const uint32_t kB = sb + (uint32_t)(128 * ROWB) + koff;
    const uint32_t vB = sb + (uint32_t)(192 * ROWB) + voff;
    const uint32_t pA = sb + (uint32_t)((256 + qrow) * ROWB) + aoff;

    float acc_o[8][4];
    #pragma unroll
    for (int nt = 0; nt < 8; nt++)
        #pragma unroll
        for (int j = 0; j < 4; j++) acc_o[nt][j] = 0.f;
    float m0 = -3.4e38f, m1 = -3.4e38f, l0 = 0.f, l1 = 0.f;

    for (int k0 = 0; k0 < NS; k0 += 64) {
        __syncthreads();   // protect Ks/Vs overwrite vs previous tile's reads

        // Load K and V tiles (natural [key][d]) as bf16
        {
            const int r = t >> 2;             // key 0..63
            const int dbase = (t & 3) * 16;
            #pragma unroll
            for (int i = 0; i < 4; i++) {
                int d0 = dbase + i * 4;
                float4 kv = *(const float4*)(Kg + (long)(k0 + r) * ND + d0);
                Ks[r * FW + (d0 >> 1)]     = pack_bf2(kv.x, kv.y);
                Ks[r * FW + (d0 >> 1) + 1] = pack_bf2(kv.z, kv.w);
                float4 vv = *(const float4*)(Vg + (long)(k0 + r) * ND + d0);
                Vs[r * FW + (d0 >> 1)]     = pack_bf2(vv.x, vv.y);
                Vs[r * FW + (d0 >> 1) + 1] = pack_bf2(vv.z, vv.w);
            }
        }
        __syncthreads();

        // ---- S = Q @ K^T (16 x 64 per warp), k-dim = d (4 blocks of 16) ----
        float acc_s[8][4];
        #pragma unroll
        for (int nt = 0; nt < 8; nt++)
            #pragma unroll
            for (int j = 0; j < 4; j++) acc_s[nt][j] = 0.f;

        #pragma unroll
        for (int ks = 0; ks < 4; ks++) {
            uint32_t a[4];
            ldsm_x4(a, qA + ks * 32);
            #pragma unroll
            for (int nt2 = 0; nt2 < 4; nt2++) {
                uint32_t bb[4];
                ldsm_x4(bb, kB + nt2 * (16 * ROWB) + ks * 32);
                mma_bf16(acc_s[nt2 * 2],     a, bb[0], bb[1]);
                mma_bf16(acc_s[nt2 * 2 + 1], a, bb[2], bb[3]);
            }
        }

        // ---- scale + mask + online softmax ----
        float mx0 = -3.4e38f, mx1 = -3.4e38f;
        #pragma unroll
        for (int nt = 0; nt < 8; nt++) {
            float2 mk = *(const float2*)&Ms[k0 + nt * 8 + lr * 2];
            acc_s[nt][0] = fmaf(acc_s[nt][0], 0.125f, mk.x);
            acc_s[nt][1] = fmaf(acc_s[nt][1], 0.125f, mk.y);
            acc_s[nt][2] = fmaf(acc_s[nt][2], 0.125f, mk.x);
            acc_s[nt][3] = fmaf(acc_s[nt][3], 0.125f, mk.y);
            mx0 = fmaxf(mx0, fmaxf(acc_s[nt][0], acc_s[nt][1]));
            mx1 = fmaxf(mx1, fmaxf(acc_s[nt][2], acc_s[nt][3]));
        }
        mx0 = fmaxf(mx0, __shfl_xor_sync(0xffffffffu, mx0, 1));
        mx0 = fmaxf(mx0, __shfl_xor_sync(0xffffffffu, mx0, 2));
        mx1 = fmaxf(mx1, __shfl_xor_sync(0xffffffffu, mx1, 1));
        mx1 = fmaxf(mx1, __shfl_xor_sync(0xffffffffu, mx1, 2));

        const float mn0 = fmaxf(m0, mx0);
        const float mn1 = fmaxf(m1, mx1);
        const float corr0 = __expf(m0 - mn0);
        const float corr1 = __expf(m1 - mn1);
        m0 = mn0; m1 = mn1;

        float ls0 = 0.f, ls1 = 0.f;
        #pragma unroll
        for (int nt = 0; nt < 8; nt++) {
            // P in bf16; l summed from the bf16-rounded values (num/den consistency)
            __nv_bfloat162 pb0 = __floats2bfloat162_rn(__expf(acc_s[nt][0] - mn0),
                                                       __expf(acc_s[nt][1] - mn0));
            __nv_bfloat162 pb1 = __floats2bfloat162_rn(__expf(acc_s[nt][2] - mn1),
                                                       __expf(acc_s[nt][3] - mn1));
            ls0 += __bfloat162float(pb0.x) + __bfloat162float(pb0.y);
            ls1 += __bfloat162float(pb1.x) + __bfloat162float(pb1.y);
            Ps[(qrow + lq) * FW + nt * 4 + lr]     = *(uint32_t*)&pb0;
            Ps[(qrow + lq + 8) * FW + nt * 4 + lr] = *(uint32_t*)&pb1;
        }
        ls0 += __shfl_xor_sync(0xffffffffu, ls0, 1);
        ls0 += __shfl_xor_sync(0xffffffffu, ls0, 2);
        ls1 += __shfl_xor_sync(0xffffffffu, ls1, 1);
        ls1 += __shfl_xor_sync(0xffffffffu, ls1, 2);
        l0 = l0 * corr0 + ls0;
        l1 = l1 * corr1 + ls1;

        #pragma unroll
        for (int nt = 0; nt < 8; nt++) {
            acc_o[nt][0] *= corr0;
            acc_o[nt][1] *= corr0;
            acc_o[nt][2] *= corr1;
            acc_o[nt][3] *= corr1;
        }
        __syncwarp();   // Ps STS -> LDSM (cross-lane within warp)

        // ---- O += P @ V, k-dim = key (4 blocks of 16) ----
        #pragma unroll
        for (int kb = 0; kb < 4; kb++) {
            uint32_t a[4];
            ldsm_x4(a, pA + kb * 32);
            #pragma unroll
            for (int nd2 = 0; nd2 < 4; nd2++) {
                uint32_t bb[4];
                ldsm_x4_t(bb, vB + kb * (16 * ROWB) + nd2 * 32);
                mma_bf16(acc_o[nd2 * 2],     a, bb[0], bb[1]);
                mma_bf16(acc_o[nd2 * 2 + 1], a, bb[2], bb[3]);
            }
        }
    }

    // ---- epilogue: normalize, head_mask, write ctx ----
    const float hm = head_mask[h];
    const float inv0 = hm / l0;
    const float inv1 = hm / l1;
    #pragma unroll
    for (int nt = 0; nt < 8; nt++) {
        const int col = h * NHD + nt * 8 + lr * 2;
        const long r0 = (long)b * NS + q0 + qrow + lq;
        *(float2*)(Cx + r0 * ND + col) =
            make_float2(acc_o[nt][0] * inv0, acc_o[nt][1] * inv0);
        *(float2*)(Cx + (r0 + 8) * ND + col) =
            make_float2(acc_o[nt][2] * inv1, acc_o[nt][3] * inv1);
    }
}

// ---------------- residual + LayerNorm ----------------
__global__ __launch_bounds__(256)
void ln_kernel(const float* __restrict__ proj, const float* __restrict__ hidden,
               const float* __restrict__ gamma, const float* __restrict__ beta,
               float* __restrict__ out)
{
    const long row = blockIdx.x;
    const int t = threadIdx.x;
    float x[3];
    #pragma unroll
    for (int k = 0; k < 3; k++) {
        long idx = row * ND + t + k * 256;
        x[k] = proj[idx] + hidden[idx];
    }
    float s = x[0] + x[1] + x[2];
    float mu = blockSum(s) * (1.0f / ND);
    float vs = 0.f;
    #pragma unroll
    for (int k = 0; k < 3; k++) { float d = x[k] - mu; vs += d * d; }
    float var = blockSum(vs) * (1.0f / ND);
    float rstd = rsqrtf(var + 1e-12f);
    #pragma unroll
    for (int k = 0; k < 3; k++) {
        int c = t + k * 256;
        out[row * ND + c] = (x[k] - mu) * rstd * gamma[c] + beta[c];
    }
}

// ---------------- launch ----------------
extern "C" void kernel_launch(void* const* d_in, const int* in_sizes, int n_in,
                              void* d_out, int out_size)
{
    const float* hidden    = (const float*)d_in[0];
    const float* attn_mask = (const float*)d_in[1];
    const float* head_mask = (const float*)d_in[2];
    const float* Wq = (const float*)d_in[3];
    const float* bq = (const float*)d_in[4];
    const float* Wk = (const float*)d_in[5];
    const float* bk = (const float*)d_in[6];
    const float* Wv = (const float*)d_in[7];
    const float* bv = (const float*)d_in[8];
    const float* Wo = (const float*)d_in[9];
    const float* bo = (const float*)d_in[10];
    const float* gamma = (const float*)d_in[11];
    const float* beta  = (const float*)d_in[12];
    float* out = (float*)d_out;

    void *pq, *pk, *pv, *pc, *pp;
    cudaGetSymbolAddress(&pq, g_q);
    cudaGetSymbolAddress(&pk, g_k);
    cudaGetSymbolAddress(&pv, g_v);
    cudaGetSymbolAddress(&pc, g_ctx);
    cudaGetSymbolAddress(&pp, g_proj);
    float* q  = (float*)pq;
    float* k  = (float*)pk;
    float* v  = (float*)pv;
    float* cx = (float*)pc;
    float* pr = (float*)pp;

    const int FLASH_SMEM = (128*FW + 64*FW + 64*FW + 128*FW) * 4 + 4096;  // 59392 B
    const int GEMM_SMEM  = 4 * 128 * SROW * 4;                            // 73728 B
    static int attr_set = 0;
    if (!attr_set) {
        cudaFuncSetAttribute(flash_bf16_kernel,
                             cudaFuncAttributeMaxDynamicSharedMemorySize, FLASH_SMEM);
        cudaFuncSetAttribute(tf32_gemm_nt_bias,
                             cudaFuncAttributeMaxDynamicSharedMemorySize, GEMM_SMEM);
        attr_set = 1;
    }

    dim3 gGemm(ND / 128, NM / 128);   // (6, 64)
    tf32_gemm_nt_bias<<<gGemm, 256, GEMM_SMEM>>>(hidden, Wq, bq, q, NM, ND);
    tf32_gemm_nt_bias<<<gGemm, 256, GEMM_SMEM>>>(hidden, Wk, bk, k, NM, ND);
    tf32_gemm_nt_bias<<<gGemm, 256, GEMM_SMEM>>>(hidden, Wv, bv, v, NM, ND);

    dim3 gF(NS / 128, NBH);           // (8, 96)
    flash_bf16_kernel<<<gF, 256, FLASH_SMEM>>>(q, k, v, attn_mask, head_mask, cx);

    tf32_gemm_nt_bias<<<gGemm, 256, GEMM_SMEM>>>(cx, Wo, bo, pr, NM, ND);

    ln_kernel<<<NM, 256>>>(pr, hidden, gamma, beta, out);
}